// round 1
// baseline (speedup 1.0000x reference)
#include <cuda_runtime.h>
#include <math.h>
#include <float.h>

#define NB 4
#define NP 4096
#define ND 768
#define NK 8
#define NH 128
#define NS 64
#define NHG 64
#define LNEPS 1e-5f

// ---- scratch (no allocations allowed) ----
__device__ float g_sums[NB*NS*ND];
__device__ float g_cnt [NB*NS];
__device__ float g_agg [NB*NS*ND];
__device__ int   g_knn [NB*NP*NK];

// ---------------------------------------------------------------------------
// zero accumulators (graph replays re-run everything)
// ---------------------------------------------------------------------------
__global__ void k_zero() {
    int i = blockIdx.x*256 + threadIdx.x;
    if (i < NB*NS*ND) g_sums[i] = 0.f;
    if (i < NB*NS)    g_cnt[i]  = 0.f;
}

// ---------------------------------------------------------------------------
// segment sums + counts via atomics
// ---------------------------------------------------------------------------
__global__ void k_seg(const float* __restrict__ feat, const int* __restrict__ lab) {
    int pi = blockIdx.x;              // 0..B*N-1
    int b  = pi >> 12;
    int l  = lab[pi];
    float* dst = g_sums + (size_t)(b*NS + l)*ND;
    const float* src = feat + (size_t)pi*ND;
    for (int d = threadIdx.x; d < ND; d += blockDim.x)
        atomicAdd(dst + d, src[d]);
    if (threadIdx.x == 0) atomicAdd(&g_cnt[b*NS + l], 1.f);
}

// ---------------------------------------------------------------------------
// superpoint MLP: means -> relu(ln(.@A1+ab1)) -> ln(.@A2+ab2) -> g_agg
// one block per (b,s) row
// ---------------------------------------------------------------------------
__global__ __launch_bounds__(256) void k_agg(
    const float* __restrict__ A1, const float* __restrict__ ab1,
    const float* __restrict__ ag1, const float* __restrict__ abt1,
    const float* __restrict__ A2, const float* __restrict__ ab2,
    const float* __restrict__ ag2, const float* __restrict__ abt2)
{
    __shared__ float mrow[ND];
    __shared__ float ah[NH];
    __shared__ float y2[ND];
    __shared__ float red_m, red_i;
    int row = blockIdx.x;             // b*S + s
    int t = threadIdx.x;

    float cnt = g_cnt[row];
    float denom = fmaxf(cnt, 1.f);
    float inv_den = 1.f / denom;
    for (int d = t; d < ND; d += 256)
        mrow[d] = g_sums[(size_t)row*ND + d] * inv_den;
    __syncthreads();

    // layer 1: (768) @ (768x128)
    if (t < NH) {
        float acc = ab1[t];
        #pragma unroll 4
        for (int j = 0; j < ND; j++)
            acc = fmaf(mrow[j], A1[j*NH + t], acc);
        ah[t] = acc;
    }
    __syncthreads();
    if (t < 32) {
        float s = 0.f, ss = 0.f;
        #pragma unroll
        for (int q = 0; q < 4; q++) { float v = ah[t + 32*q]; s += v; ss = fmaf(v, v, ss); }
        #pragma unroll
        for (int o = 16; o; o >>= 1) { s += __shfl_xor_sync(0xffffffffu, s, o); ss += __shfl_xor_sync(0xffffffffu, ss, o); }
        if (t == 0) { float m = s*(1.f/NH); red_m = m; red_i = rsqrtf(ss*(1.f/NH) - m*m + LNEPS); }
    }
    __syncthreads();
    if (t < NH) {
        float v = fmaf((ah[t]-red_m)*red_i, ag1[t], abt1[t]);
        ah[t] = fmaxf(v, 0.f);
    }
    __syncthreads();

    // layer 2: (128) @ (128x768)
    for (int d = t; d < ND; d += 256) {
        float acc = ab2[d];
        #pragma unroll 4
        for (int j = 0; j < NH; j++)
            acc = fmaf(ah[j], A2[j*ND + d], acc);
        y2[d] = acc;
    }
    __syncthreads();
    if (t < 32) {
        float s = 0.f, ss = 0.f;
        #pragma unroll
        for (int q = 0; q < 24; q++) { float v = y2[t + 32*q]; s += v; ss = fmaf(v, v, ss); }
        #pragma unroll
        for (int o = 16; o; o >>= 1) { s += __shfl_xor_sync(0xffffffffu, s, o); ss += __shfl_xor_sync(0xffffffffu, ss, o); }
        if (t == 0) { float m = s*(1.f/ND); red_m = m; red_i = rsqrtf(ss*(1.f/ND) - m*m + LNEPS); }
    }
    __syncthreads();
    for (int d = t; d < ND; d += 256)
        g_agg[(size_t)row*ND + d] = fmaf((y2[d]-red_m)*red_i, ag2[d], abt2[d]);
}

// ---------------------------------------------------------------------------
// brute-force KNN (K+1 incl. self, sorted ascending; emit ranks 1..8)
// grid (N/128, B), 128 threads, candidate tiles of 1024 in shared
// ---------------------------------------------------------------------------
__global__ __launch_bounds__(128) void k_knn(const float* __restrict__ coords) {
    __shared__ float4 sh[1024];
    int b = blockIdx.y;
    int q = blockIdx.x*128 + threadIdx.x;
    const float* cb = coords + (size_t)b*NP*3;
    float qx = cb[q*3+0], qy = cb[q*3+1], qz = cb[q*3+2];

    float bd[9]; int bi[9];
    #pragma unroll
    for (int i = 0; i < 9; i++) { bd[i] = FLT_MAX; bi[i] = 0x7fffffff; }

    for (int tile = 0; tile < 4; tile++) {
        __syncthreads();
        for (int i = threadIdx.x; i < 1024; i += 128) {
            int jj = tile*1024 + i;
            sh[i] = make_float4(cb[jj*3+0], cb[jj*3+1], cb[jj*3+2], 0.f);
        }
        __syncthreads();
        #pragma unroll 4
        for (int j = 0; j < 1024; j++) {
            float4 c = sh[j];
            float dx = qx - c.x, dy = qy - c.y, dz = qz - c.z;
            float d2 = dx*dx + dy*dy + dz*dz;
            int jj = tile*1024 + j;
            if (d2 < bd[8] || (d2 == bd[8] && jj < bi[8])) {
                int pos = 8;
                #pragma unroll
                for (int p = 7; p >= 0; p--) {
                    bool mv = (d2 < bd[p]) || (d2 == bd[p] && jj < bi[p]);
                    if (mv) { bd[p+1] = bd[p]; bi[p+1] = bi[p]; pos = p; }
                }
                bd[pos] = d2; bi[pos] = jj;
            }
        }
    }
    int* dst = g_knn + (size_t)(b*NP + q)*NK;
    #pragma unroll
    for (int k = 0; k < NK; k++) dst[k] = bi[k+1];
}

// ---------------------------------------------------------------------------
// fused main kernel: geom -> ln/relu MLP1 -> GEMM(32x768x64) -> ln -> mean_k
//                    -> final blend with segment agg -> out
// one block per 4 points (32 rows of (point,k)), 512 threads
// ---------------------------------------------------------------------------
__global__ __launch_bounds__(512) void k_main(
    const float* __restrict__ coords, const float* __restrict__ feat,
    const int* __restrict__ lab,
    const float* __restrict__ W1, const float* __restrict__ b1,
    const float* __restrict__ g1, const float* __restrict__ bt1,
    const float* __restrict__ W2, const float* __restrict__ b2,
    const float* __restrict__ g2, const float* __restrict__ bt2,
    float* __restrict__ out)
{
    extern __shared__ float sm[];
    float* y_s = sm;                    // 32*768
    float* h_s = y_s + 32*ND;           // 32*64
    float* geo = h_s + 32*NHG;          // 32*4
    float* m_s = geo + 128;             // 32
    float* v_s = m_s + 32;              // 32
    const int t = threadIdx.x;
    const int p0 = blockIdx.x * 4;      // global point index base (b*N+n)

    // A: geometry per (point,k) row
    if (t < 32) {
        int lp = t >> 3, k = t & 7;
        int gp = p0 + lp;
        int b  = gp >> 12;
        int ni = g_knn[gp*NK + k];
        const float* cq = coords + (size_t)gp*3;
        const float* cn = coords + ((size_t)(b << 12) + ni)*3;
        float dx = cn[0]-cq[0], dy = cn[1]-cq[1], dz = cn[2]-cq[2];
        float rd = sqrtf(dx*dx + dy*dy + dz*dz);
        geo[t*4+0] = rd; geo[t*4+1] = dx; geo[t*4+2] = dy; geo[t*4+3] = fminf(rd, 1.f);
    }
    __syncthreads();

    // B: hpre = geom @ W1 + b1  (32 rows x 64)
    {
        int r  = t >> 4;           // 0..31
        int c0 = (t & 15) * 4;     // 0..60
        float gA = geo[r*4+0], gB = geo[r*4+1], gC = geo[r*4+2], gD = geo[r*4+3];
        #pragma unroll
        for (int cc = 0; cc < 4; cc++) {
            int c = c0 + cc;
            float v = b1[c];
            v = fmaf(gA, W1[c], v);
            v = fmaf(gB, W1[NHG + c], v);
            v = fmaf(gC, W1[2*NHG + c], v);
            v = fmaf(gD, W1[3*NHG + c], v);
            h_s[r*NHG + c] = v;
        }
    }
    __syncthreads();

    // C: LN stats per h-row
    if (t < 32) {
        float s = 0.f, ss = 0.f;
        #pragma unroll 8
        for (int c = 0; c < NHG; c++) { float v = h_s[t*NHG + c]; s += v; ss = fmaf(v, v, ss); }
        float m = s * (1.f/NHG);
        m_s[t] = m;
        v_s[t] = rsqrtf(ss*(1.f/NHG) - m*m + LNEPS);
    }
    __syncthreads();

    // D: apply LN + affine + relu in place
    for (int idx = t; idx < 32*NHG; idx += 512) {
        int r = idx >> 6, c = idx & 63;
        float v = (h_s[idx] - m_s[r]) * v_s[r];
        h_s[idx] = fmaxf(fmaf(v, g1[c], bt1[c]), 0.f);
    }
    __syncthreads();

    // E: y = h @ W2 + b2   (32 x 768, k = 64). W2 column cached in registers.
    {
        const int dlane = t & 255;
        const int r0 = (t >> 8) * 16;
        #pragma unroll 1
        for (int pass = 0; pass < 3; pass++) {
            int d = pass*256 + dlane;
            float w[64];
            #pragma unroll
            for (int j = 0; j < 64; j++) w[j] = W2[j*ND + d];
            float bb = b2[d];
            #pragma unroll 2
            for (int r = r0; r < r0 + 16; r++) {
                const float4* h4 = reinterpret_cast<const float4*>(h_s + (r << 6));
                float a0 = 0.f, a1 = 0.f, a2 = 0.f, a3 = 0.f;
                #pragma unroll
                for (int q = 0; q < 16; q += 4) {
                    float4 u0 = h4[q], u1 = h4[q+1], u2 = h4[q+2], u3 = h4[q+3];
                    a0 = fmaf(u0.x, w[4*q+ 0], fmaf(u0.y, w[4*q+ 1], fmaf(u0.z, w[4*q+ 2], fmaf(u0.w, w[4*q+ 3], a0))));
                    a1 = fmaf(u1.x, w[4*q+ 4], fmaf(u1.y, w[4*q+ 5], fmaf(u1.z, w[4*q+ 6], fmaf(u1.w, w[4*q+ 7], a1))));
                    a2 = fmaf(u2.x, w[4*q+ 8], fmaf(u2.y, w[4*q+ 9], fmaf(u2.z, w[4*q+10], fmaf(u2.w, w[4*q+11], a2))));
                    a3 = fmaf(u3.x, w[4*q+12], fmaf(u3.y, w[4*q+13], fmaf(u3.z, w[4*q+14], fmaf(u3.w, w[4*q+15], a3))));
                }
                y_s[r*ND + d] = bb + ((a0 + a1) + (a2 + a3));
            }
        }
    }
    __syncthreads();

    // F: LN stats per y-row (warp per 2 rows)
    {
        int wid = t >> 5, lane = t & 31;
        #pragma unroll
        for (int rr = 0; rr < 2; rr++) {
            int r = wid*2 + rr;
            float s = 0.f, ss = 0.f;
            #pragma unroll
            for (int q = 0; q < 24; q++) { float v = y_s[r*ND + lane + 32*q]; s += v; ss = fmaf(v, v, ss); }
            #pragma unroll
            for (int o = 16; o; o >>= 1) { s += __shfl_xor_sync(0xffffffffu, s, o); ss += __shfl_xor_sync(0xffffffffu, ss, o); }
            if (lane == 0) { float m = s*(1.f/ND); m_s[r] = m; v_s[r] = rsqrtf(ss*(1.f/ND) - m*m + LNEPS); }
        }
    }
    __syncthreads();

    // G: gctx = mean_k ln(y); out = blend(features, agg) + 0.1*gctx
    for (int idx = t; idx < 4*ND; idx += 512) {
        int lp = idx / ND, d = idx - lp*ND;
        float gbar = 0.f;
        #pragma unroll
        for (int k = 0; k < NK; k++) {
            int r = lp*NK + k;
            gbar += (y_s[r*ND + d] - m_s[r]) * v_s[r];
        }
        gbar *= 0.125f;
        int gp = p0 + lp;
        int b  = gp >> 12;
        int l  = lab[gp];
        float cnt = g_cnt[b*NS + l];
        float a   = g_agg[(size_t)(b*NS + l)*ND + d];
        float f   = feat[(size_t)gp*ND + d];
        float e   = (cnt >= 2.f) ? fmaf(0.1f, a, 0.9f*f) : f;
        out[(size_t)gp*ND + d] = fmaf(0.1f, fmaf(gbar, g2[d], bt2[d]), e);
    }
}

// ---------------------------------------------------------------------------
extern "C" void kernel_launch(void* const* d_in, const int* in_sizes, int n_in,
                              void* d_out, int out_size) {
    const float* coords = (const float*)d_in[0];
    const float* feat   = (const float*)d_in[1];
    const int*   lab    = (const int*)  d_in[2];
    const float* W1     = (const float*)d_in[3];
    const float* b1     = (const float*)d_in[4];
    const float* g1     = (const float*)d_in[5];
    const float* bt1    = (const float*)d_in[6];
    const float* W2     = (const float*)d_in[7];
    const float* b2     = (const float*)d_in[8];
    const float* g2     = (const float*)d_in[9];
    const float* bt2    = (const float*)d_in[10];
    const float* A1     = (const float*)d_in[11];
    const float* ab1    = (const float*)d_in[12];
    const float* ag1    = (const float*)d_in[13];
    const float* abt1   = (const float*)d_in[14];
    const float* A2     = (const float*)d_in[15];
    const float* ab2    = (const float*)d_in[16];
    const float* ag2    = (const float*)d_in[17];
    const float* abt2   = (const float*)d_in[18];
    float* out = (float*)d_out;

    static int smem_set = 0;
    const int SMEM_MAIN = (32*ND + 32*NHG + 128 + 64) * 4;  // 107264 B
    if (!smem_set) {
        cudaFuncSetAttribute(k_main, cudaFuncAttributeMaxDynamicSharedMemorySize, SMEM_MAIN);
        smem_set = 1;
    }

    k_zero<<<(NB*NS*ND + 255)/256, 256>>>();
    k_seg<<<NB*NP, 256>>>(feat, lab);
    k_agg<<<NB*NS, 256>>>(A1, ab1, ag1, abt1, A2, ab2, ag2, abt2);
    k_knn<<<dim3(NP/128, NB), 128>>>(coords);
    k_main<<<(NB*NP)/4, 512, SMEM_MAIN>>>(coords, feat, lab,
                                          W1, b1, g1, bt1, W2, b2, g2, bt2, out);
}

// round 2
// speedup vs baseline: 2.0194x; 2.0194x over previous
#include <cuda_runtime.h>
#include <math.h>
#include <float.h>

#define NB 4
#define NP 4096
#define ND 768
#define NK 8
#define NH 128
#define NS 64
#define NHG 64
#define LNEPS 1e-5f

typedef unsigned long long u64;

// ---- scratch (no allocations allowed) ----
__device__ float g_sums[NB*NS*ND];
__device__ float g_cnt [NB*NS];
__device__ float g_agg [NB*NS*ND];
__device__ int   g_knn [NB*NP*NK];
__device__ float g_G   [NHG*NHG];   // W2 @ W2^T
__device__ float g_u   [NHG];       // mean_d W2[j,d]
__device__ float g_c   [NHG];       // sum_d W2[j,d]*b2[d]
__device__ float g_sb2;             // sum_d b2[d]^2
__device__ float g_bm;              // mean(b2)

// ---------------------------------------------------------------------------
__global__ void k_zero() {
    int i = blockIdx.x*256 + threadIdx.x;
    if (i < NB*NS*ND) g_sums[i] = 0.f;
    if (i < NB*NS)    g_cnt[i]  = 0.f;
}

// ---------------------------------------------------------------------------
// precompute Gram matrix G = W2 W2^T, u, c, sb2, bm
// grid 64 blocks x 128 threads; block i handles row i
// ---------------------------------------------------------------------------
__global__ __launch_bounds__(128) void k_prep(const float* __restrict__ W2,
                                              const float* __restrict__ b2) {
    __shared__ float red[128];
    int i = blockIdx.x, t = threadIdx.x;
    int j = t & 63, half = t >> 6;
    const float* wi = W2 + (size_t)i*ND;
    const float* wj = W2 + (size_t)j*ND;
    float s = 0.f;
    for (int d = half*384; d < half*384 + 384; d++)
        s = fmaf(wi[d], wj[d], s);
    red[t] = s;
    __syncthreads();
    if (half == 0) g_G[i*NHG + j] = red[j] + red[64 + j];
    __syncthreads();

    // u_i and c_i (reduce over full row i)
    float su = 0.f, sc = 0.f;
    for (int d = t; d < ND; d += 128) { float w = wi[d]; su += w; sc = fmaf(w, b2[d], sc); }
    red[t] = su; __syncthreads();
    if (t < 64) red[t] += red[t+64]; __syncthreads();
    if (t < 32) red[t] += red[t+32]; __syncthreads();
    if (t == 0) { float a=0; for (int q=0;q<32;q++) a+=red[q]; g_u[i] = a * (1.f/ND); }
    __syncthreads();
    red[t] = sc; __syncthreads();
    if (t < 64) red[t] += red[t+64]; __syncthreads();
    if (t < 32) red[t] += red[t+32]; __syncthreads();
    if (t == 0) { float a=0; for (int q=0;q<32;q++) a+=red[q]; g_c[i] = a; }

    if (i == 0) {
        __syncthreads();
        float s2 = 0.f, sb = 0.f;
        for (int d = t; d < ND; d += 128) { float bv = b2[d]; s2 = fmaf(bv,bv,s2); sb += bv; }
        red[t] = s2; __syncthreads();
        if (t < 64) red[t] += red[t+64]; __syncthreads();
        if (t < 32) red[t] += red[t+32]; __syncthreads();
        if (t == 0) { float a=0; for (int q=0;q<32;q++) a+=red[q]; g_sb2 = a; }
        __syncthreads();
        red[t] = sb; __syncthreads();
        if (t < 64) red[t] += red[t+64]; __syncthreads();
        if (t < 32) red[t] += red[t+32]; __syncthreads();
        if (t == 0) { float a=0; for (int q=0;q<32;q++) a+=red[q]; g_bm = a * (1.f/ND); }
    }
}

// ---------------------------------------------------------------------------
// segment sums via shared-memory binning: each thread owns one d column
// grid (6 chunks, 8 point-ranges, B), 128 threads
// ---------------------------------------------------------------------------
__global__ __launch_bounds__(128) void k_seg(const float* __restrict__ feat,
                                             const int* __restrict__ lab) {
    __shared__ float bins[NS*128];
    __shared__ int slab[512];
    __shared__ int scnt[NS];
    int chunk = blockIdx.x, rg = blockIdx.y, b = blockIdx.z;
    int t = threadIdx.x;
    int d = chunk*128 + t;

    for (int i = t; i < NS*128; i += 128) bins[i] = 0.f;
    if (chunk == 0 && t < NS) scnt[t] = 0;
    for (int i = t; i < 512; i += 128) slab[i] = lab[b*NP + rg*512 + i];
    __syncthreads();

    const float* fb = feat + ((size_t)(b*NP + rg*512))*ND + d;
    #pragma unroll 1
    for (int pp = 0; pp < 512; pp += 4) {
        int l0 = slab[pp+0], l1 = slab[pp+1], l2 = slab[pp+2], l3 = slab[pp+3];
        float v0 = fb[(size_t)(pp+0)*ND];
        float v1 = fb[(size_t)(pp+1)*ND];
        float v2 = fb[(size_t)(pp+2)*ND];
        float v3 = fb[(size_t)(pp+3)*ND];
        bins[l0*128 + t] += v0;
        bins[l1*128 + t] += v1;
        bins[l2*128 + t] += v2;
        bins[l3*128 + t] += v3;
    }
    if (chunk == 0) {
        #pragma unroll
        for (int r = 0; r < 4; r++) atomicAdd(&scnt[slab[t + 128*r]], 1);
    }
    __syncthreads();

    for (int l = 0; l < NS; l++)
        atomicAdd(&g_sums[((size_t)(b*NS + l))*ND + d], bins[l*128 + t]);
    if (chunk == 0 && t < NS)
        atomicAdd(&g_cnt[b*NS + t], (float)scnt[t]);
}

// ---------------------------------------------------------------------------
// superpoint MLP (unchanged; cheap)
// ---------------------------------------------------------------------------
__global__ __launch_bounds__(256) void k_agg(
    const float* __restrict__ A1, const float* __restrict__ ab1,
    const float* __restrict__ ag1, const float* __restrict__ abt1,
    const float* __restrict__ A2, const float* __restrict__ ab2,
    const float* __restrict__ ag2, const float* __restrict__ abt2)
{
    __shared__ float mrow[ND];
    __shared__ float ah[NH];
    __shared__ float y2[ND];
    __shared__ float red_m, red_i;
    int row = blockIdx.x;
    int t = threadIdx.x;

    float inv_den = 1.f / fmaxf(g_cnt[row], 1.f);
    for (int d = t; d < ND; d += 256)
        mrow[d] = g_sums[(size_t)row*ND + d] * inv_den;
    __syncthreads();

    if (t < NH) {
        float acc = ab1[t];
        #pragma unroll 4
        for (int j = 0; j < ND; j++)
            acc = fmaf(mrow[j], A1[j*NH + t], acc);
        ah[t] = acc;
    }
    __syncthreads();
    if (t < 32) {
        float s = 0.f, ss = 0.f;
        #pragma unroll
        for (int q = 0; q < 4; q++) { float v = ah[t + 32*q]; s += v; ss = fmaf(v, v, ss); }
        #pragma unroll
        for (int o = 16; o; o >>= 1) { s += __shfl_xor_sync(0xffffffffu, s, o); ss += __shfl_xor_sync(0xffffffffu, ss, o); }
        if (t == 0) { float m = s*(1.f/NH); red_m = m; red_i = rsqrtf(ss*(1.f/NH) - m*m + LNEPS); }
    }
    __syncthreads();
    if (t < NH) {
        float v = fmaf((ah[t]-red_m)*red_i, ag1[t], abt1[t]);
        ah[t] = fmaxf(v, 0.f);
    }
    __syncthreads();

    for (int d = t; d < ND; d += 256) {
        float acc = ab2[d];
        #pragma unroll 4
        for (int j = 0; j < NH; j++)
            acc = fmaf(ah[j], A2[j*ND + d], acc);
        y2[d] = acc;
    }
    __syncthreads();
    if (t < 32) {
        float s = 0.f, ss = 0.f;
        #pragma unroll
        for (int q = 0; q < 24; q++) { float v = y2[t + 32*q]; s += v; ss = fmaf(v, v, ss); }
        #pragma unroll
        for (int o = 16; o; o >>= 1) { s += __shfl_xor_sync(0xffffffffu, s, o); ss += __shfl_xor_sync(0xffffffffu, ss, o); }
        if (t == 0) { float m = s*(1.f/ND); red_m = m; red_i = rsqrtf(ss*(1.f/ND) - m*m + LNEPS); }
    }
    __syncthreads();
    for (int d = t; d < ND; d += 256)
        g_agg[(size_t)row*ND + d] = fmaf((y2[d]-red_m)*red_i, ag2[d], abt2[d]);
}

// ---------------------------------------------------------------------------
// KNN: warp per query, lanes split candidates, packed (d2,idx) u64 top-9,
// warp-shuffle merge of sorted per-lane lists. grid (256, B), 512 threads.
// ---------------------------------------------------------------------------
__global__ __launch_bounds__(512) void k_knn(const float* __restrict__ coords) {
    __shared__ float4 sh[1024];
    int b = blockIdx.y;
    int w = threadIdx.x >> 5, lane = threadIdx.x & 31;
    int q = blockIdx.x*16 + w;
    const float* cb = coords + (size_t)b*NP*3;
    float qx = cb[q*3+0], qy = cb[q*3+1], qz = cb[q*3+2];

    u64 arr[9];
    #pragma unroll
    for (int i = 0; i < 9; i++) arr[i] = ~0ull;

    for (int tile = 0; tile < 4; tile++) {
        __syncthreads();
        for (int i = threadIdx.x; i < 1024; i += 512) {
            int jj = tile*1024 + i;
            sh[i] = make_float4(cb[jj*3+0], cb[jj*3+1], cb[jj*3+2], 0.f);
        }
        __syncthreads();
        #pragma unroll 4
        for (int j = lane; j < 1024; j += 32) {
            float4 c = sh[j];
            float dx = qx - c.x, dy = qy - c.y, dz = qz - c.z;
            float d2 = fmaf(dx,dx, fmaf(dy,dy, dz*dz));
            int jj = tile*1024 + j;
            u64 u = ((u64)__float_as_uint(d2) << 32) | (unsigned)jj;
            if (u < arr[8]) {
                arr[8] = u;
                #pragma unroll
                for (int p = 8; p > 0; p--) {
                    u64 a = arr[p-1], bb = arr[p];
                    if (bb < a) { arr[p] = a; arr[p-1] = bb; }
                }
            }
        }
    }

    // merge: 9 rounds of warp-min over lane heads
    int* dst = g_knn + ((size_t)(b*NP + q))*NK;
    #pragma unroll
    for (int r = 0; r < 9; r++) {
        u64 m = arr[0];
        #pragma unroll
        for (int o = 16; o; o >>= 1) {
            u64 ot = __shfl_xor_sync(0xffffffffu, m, o);
            m = (ot < m) ? ot : m;
        }
        bool win = (arr[0] == m);
        if (win) {
            #pragma unroll
            for (int p = 0; p < 8; p++) arr[p] = arr[p+1];
            arr[8] = ~0ull;
        }
        if (lane == 0 && r > 0) dst[r-1] = (int)(m & 0xffffffffull);
    }
}

// ---------------------------------------------------------------------------
// fused main kernel (Gram-trick): 16 points / block, 256 threads
// ---------------------------------------------------------------------------
__global__ __launch_bounds__(256, 2) void k_main(
    const float* __restrict__ coords, const float* __restrict__ feat,
    const int* __restrict__ lab,
    const float* __restrict__ W1, const float* __restrict__ b1,
    const float* __restrict__ g1, const float* __restrict__ bt1,
    const float* __restrict__ W2, const float* __restrict__ b2,
    const float* __restrict__ g2, const float* __restrict__ bt2,
    float* __restrict__ out)
{
    extern __shared__ float sm[];
    float* sG   = sm;               // 4096
    float* hbar = sG + 4096;        // 1024  (16 x 64)
    float* hT   = hbar + 1024;      // 8320  (64 x 130, [j][pk])
    float* sinv = hT + 8320;        // 128
    float* smn  = sinv + 128;       // 128
    float* sS1  = smn + 128;        // 16
    float* sS2  = sS1 + 16;         // 16
    float* sCnt = sS2 + 16;         // 16
    int*   sLab = (int*)(sCnt + 16);// 16
    float* sW1  = (float*)(sLab + 16); // 256
    float* sb1  = sW1 + 256;        // 64
    float* sg1  = sb1 + 64;         // 64
    float* sbt1 = sg1 + 64;         // 64
    float* su   = sbt1 + 64;        // 64
    float* sc   = su + 64;          // 64

    const int t = threadIdx.x;
    const int p0 = blockIdx.x * 16;
    const int b  = blockIdx.x >> 8;          // 256 blocks per batch

    // ---- phase 0: stage params ----
    #pragma unroll
    for (int i = 0; i < 16; i++) sG[t + 256*i] = g_G[t + 256*i];
    sW1[t] = W1[t];
    if (t < 64) { sb1[t] = b1[t]; sg1[t] = g1[t]; sbt1[t] = bt1[t]; su[t] = g_u[t]; sc[t] = g_c[t]; }
    if (t < 16) {
        int l = lab[p0 + t];
        sLab[t] = l;
        sCnt[t] = g_cnt[b*NS + l];
    }
    __syncthreads();

    // ---- phase 1: geometry -> h (LN+relu), pairs of threads per (p,k) row ----
    {
        int pk = t >> 1, jb = (t & 1) * 32;
        int p = pk >> 3, kk = pk & 7;
        int gp = p0 + p;
        int ni = g_knn[gp*NK + kk];
        const float* cq = coords + (size_t)gp*3;
        const float* cn = coords + ((size_t)b*NP + ni)*3;
        float dx = cn[0]-cq[0], dy = cn[1]-cq[1], dz = cn[2]-cq[2];
        float rd = sqrtf(fmaf(dx,dx, fmaf(dy,dy, dz*dz)));
        float gm0 = rd, gm1 = dx, gm2 = dy, gm3 = fminf(rd, 1.f);

        float hv[32];
        float s = 0.f, ss = 0.f;
        #pragma unroll
        for (int jo = 0; jo < 32; jo++) {
            int j = jb + jo;
            float v = sb1[j];
            v = fmaf(gm0, sW1[j],       v);
            v = fmaf(gm1, sW1[64 + j],  v);
            v = fmaf(gm2, sW1[128 + j], v);
            v = fmaf(gm3, sW1[192 + j], v);
            hv[jo] = v;
            s += v; ss = fmaf(v, v, ss);
        }
        s  += __shfl_xor_sync(0xffffffffu, s, 1);
        ss += __shfl_xor_sync(0xffffffffu, ss, 1);
        float m = s * (1.f/NHG);
        float iv = rsqrtf(ss*(1.f/NHG) - m*m + LNEPS);
        #pragma unroll
        for (int jo = 0; jo < 32; jo++) {
            int j = jb + jo;
            float h = fmaxf(fmaf((hv[jo]-m)*iv, sg1[j], sbt1[j]), 0.f);
            hT[j*130 + pk] = h;
        }
    }
    __syncthreads();

    // ---- phase 2: LN stats from Gram: q = h^T G h, m = h.u, ch = h.c ----
    {
        int pk = t >> 1, jb = (t & 1) * 32;
        float acc[32];
        #pragma unroll
        for (int jo = 0; jo < 32; jo++) acc[jo] = 0.f;
        #pragma unroll 4
        for (int i = 0; i < 64; i++) {
            float hv = hT[i*130 + pk];
            const float4* gr = reinterpret_cast<const float4*>(sG + i*64 + jb);
            #pragma unroll
            for (int q4 = 0; q4 < 8; q4++) {
                float4 g4 = gr[q4];
                acc[4*q4+0] = fmaf(hv, g4.x, acc[4*q4+0]);
                acc[4*q4+1] = fmaf(hv, g4.y, acc[4*q4+1]);
                acc[4*q4+2] = fmaf(hv, g4.z, acc[4*q4+2]);
                acc[4*q4+3] = fmaf(hv, g4.w, acc[4*q4+3]);
            }
        }
        float qh = 0.f, mh = 0.f, ch = 0.f;
        #pragma unroll
        for (int jo = 0; jo < 32; jo++) {
            int j = jb + jo;
            float hj = hT[j*130 + pk];
            qh = fmaf(acc[jo], hj, qh);
            mh = fmaf(hj, su[j], mh);
            ch = fmaf(hj, sc[j], ch);
        }
        qh += __shfl_xor_sync(0xffffffffu, qh, 1);
        mh += __shfl_xor_sync(0xffffffffu, mh, 1);
        ch += __shfl_xor_sync(0xffffffffu, ch, 1);
        if ((t & 1) == 0) {
            float m  = mh + g_bm;
            float e2 = (qh + 2.f*ch + g_sb2) * (1.f/ND);
            float iv = rsqrtf(e2 - m*m + LNEPS);
            sinv[pk] = iv;
            smn[pk]  = m;
        }
    }
    __syncthreads();

    // ---- phase 3: hbar = sum_k inv_k h_k ; S1, S2 ----
    {
        #pragma unroll
        for (int qq = 0; qq < 4; qq++) {
            int o = t*4 + qq;
            int p = o >> 6, j = o & 63;
            float a = 0.f;
            #pragma unroll
            for (int k = 0; k < NK; k++)
                a = fmaf(sinv[p*NK + k], hT[j*130 + p*NK + k], a);
            hbar[p*64 + j] = a;
        }
        if (t < 16) {
            float s1 = 0.f, s2 = 0.f;
            #pragma unroll
            for (int k = 0; k < NK; k++) {
                float iv = sinv[t*NK + k];
                s1 += iv;
                s2 = fmaf(iv, smn[t*NK + k], s2);
            }
            sS1[t] = s1; sS2[t] = s2;
        }
    }
    __syncthreads();

    // ---- phase 4: gctx GEMM (hbar @ W2) + epilogue ----
    #pragma unroll 1
    for (int pass = 0; pass < 3; pass++) {
        int d = pass*256 + t;
        float w[64];
        #pragma unroll
        for (int j = 0; j < 64; j++) w[j] = W2[j*ND + d];
        float bb = b2[d], gg = g2[d], bt = bt2[d];
        float fv[16];
        #pragma unroll
        for (int p = 0; p < 16; p++) fv[p] = feat[(size_t)(p0+p)*ND + d];

        #pragma unroll 4
        for (int p = 0; p < 16; p++) {
            const float4* hb = reinterpret_cast<const float4*>(hbar + (p << 6));
            float a0 = 0.f, a1 = 0.f, a2 = 0.f, a3 = 0.f;
            #pragma unroll
            for (int q4 = 0; q4 < 16; q4 += 4) {
                float4 u0 = hb[q4], u1 = hb[q4+1], u2 = hb[q4+2], u3 = hb[q4+3];
                a0 = fmaf(u0.x, w[4*q4+ 0], fmaf(u0.y, w[4*q4+ 1], fmaf(u0.z, w[4*q4+ 2], fmaf(u0.w, w[4*q4+ 3], a0))));
                a1 = fmaf(u1.x, w[4*q4+ 4], fmaf(u1.y, w[4*q4+ 5], fmaf(u1.z, w[4*q4+ 6], fmaf(u1.w, w[4*q4+ 7], a1))));
                a2 = fmaf(u2.x, w[4*q4+ 8], fmaf(u2.y, w[4*q4+ 9], fmaf(u2.z, w[4*q4+10], fmaf(u2.w, w[4*q4+11], a2))));
                a3 = fmaf(u3.x, w[4*q4+12], fmaf(u3.y, w[4*q4+13], fmaf(u3.z, w[4*q4+14], fmaf(u3.w, w[4*q4+15], a3))));
            }
            float dot = (a0 + a1) + (a2 + a3);
            float gc  = (dot + fmaf(bb, sS1[p], -sS2[p])) * 0.125f;  // mean_k normalized
            float enc = fmaf(gc, gg, bt);
            int   l   = sLab[p];
            float a   = g_agg[((size_t)(b*NS + l))*ND + d];
            float f   = fv[p];
            float e   = (sCnt[p] >= 2.f) ? fmaf(0.1f, a, 0.9f*f) : f;
            out[(size_t)(p0+p)*ND + d] = fmaf(0.1f, enc, e);
        }
    }
}

// ---------------------------------------------------------------------------
extern "C" void kernel_launch(void* const* d_in, const int* in_sizes, int n_in,
                              void* d_out, int out_size) {
    const float* coords = (const float*)d_in[0];
    const float* feat   = (const float*)d_in[1];
    const int*   lab    = (const int*)  d_in[2];
    const float* W1     = (const float*)d_in[3];
    const float* b1     = (const float*)d_in[4];
    const float* g1     = (const float*)d_in[5];
    const float* bt1    = (const float*)d_in[6];
    const float* W2     = (const float*)d_in[7];
    const float* b2     = (const float*)d_in[8];
    const float* g2     = (const float*)d_in[9];
    const float* bt2    = (const float*)d_in[10];
    const float* A1     = (const float*)d_in[11];
    const float* ab1    = (const float*)d_in[12];
    const float* ag1    = (const float*)d_in[13];
    const float* abt1   = (const float*)d_in[14];
    const float* A2     = (const float*)d_in[15];
    const float* ab2    = (const float*)d_in[16];
    const float* ag2    = (const float*)d_in[17];
    const float* abt2   = (const float*)d_in[18];
    float* out = (float*)d_out;

    static int smem_set = 0;
    const int SMEM_MAIN = 14336 * 4;   // 57344 B
    if (!smem_set) {
        cudaFuncSetAttribute(k_main, cudaFuncAttributeMaxDynamicSharedMemorySize, SMEM_MAIN);
        smem_set = 1;
    }

    k_zero<<<(NB*NS*ND + 255)/256, 256>>>();
    k_seg <<<dim3(6, 8, NB), 128>>>(feat, lab);
    k_agg <<<NB*NS, 256>>>(A1, ab1, ag1, abt1, A2, ab2, ag2, abt2);
    k_prep<<<NHG, 128>>>(W2, b2);
    k_knn <<<dim3(NP/16, NB), 512>>>(coords);
    k_main<<<(NB*NP)/16, 256, SMEM_MAIN>>>(coords, feat, lab,
                                           W1, b1, g1, bt1, W2, b2, g2, bt2, out);
}

// round 3
// speedup vs baseline: 2.2464x; 1.1124x over previous
#include <cuda_runtime.h>
#include <math.h>
#include <float.h>

#define NB 4
#define NP 4096
#define ND 768
#define NK 8
#define NH 128
#define NS 64
#define NHG 64
#define NRG 16
#define LNEPS 1e-5f

typedef unsigned long long u64;

// ---- scratch (no allocations allowed) ----
__device__ float g_sums16[NRG*NB*NS*ND];   // per-range segment sums (written fully)
__device__ float g_cnt16 [NRG*NB*NS];
__device__ float g_cnt   [NB*NS];          // totals (written by k_agg)
__device__ float g_agg   [NB*NS*ND];
__device__ int   g_knn   [NB*NP*NK];
__device__ float g_G     [NHG*NHG];        // W2 @ W2^T
__device__ float g_u     [NHG];            // mean_d W2[j,d]
__device__ float g_c     [NHG];            // sum_d W2[j,d]*b2[d]
__device__ float g_sb2;                    // sum_d b2[d]^2
__device__ float g_bm;                     // mean(b2)

// ---------------------------------------------------------------------------
// block-wide reduce for 512 threads (red must hold 512 floats)
// ---------------------------------------------------------------------------
__device__ __forceinline__ float red512(float v, float* red, int t) {
    red[t] = v; __syncthreads();
    if (t < 256) red[t] += red[t+256]; __syncthreads();
    if (t < 128) red[t] += red[t+128]; __syncthreads();
    if (t <  64) red[t] += red[t+ 64]; __syncthreads();
    if (t <  32) {
        float s = red[t] + red[t+32];
        #pragma unroll
        for (int o = 16; o; o >>= 1) s += __shfl_xor_sync(0xffffffffu, s, o);
        if (t == 0) red[0] = s;
    }
    __syncthreads();
    float r = red[0];
    __syncthreads();
    return r;
}

// ---------------------------------------------------------------------------
// FUSED front-end kernel: blocks [0,192) seg, [192,256) prep, [256,1280) knn
// 512 threads, dynamic smem
// ---------------------------------------------------------------------------
__global__ __launch_bounds__(512) void k_pre(
    const float* __restrict__ coords, const float* __restrict__ feat,
    const int* __restrict__ lab,
    const float* __restrict__ W2, const float* __restrict__ b2)
{
    extern __shared__ char sm_raw[];
    const int bx = blockIdx.x;
    const int t  = threadIdx.x;

    if (bx < 192) {
        // ============== SEG role: chunk(3) x range(16) x batch(4) =========
        float* bins = (float*)sm_raw;          // 64*256
        int*   slab = (int*)(bins + NS*256);   // 256
        int*   scnt = slab + 256;              // 64
        int chunk = bx >> 6;          // 0..2
        int rem   = bx & 63;
        int rg    = rem >> 2;         // 0..15
        int b     = rem & 3;

        for (int i = t; i < NS*256; i += 512) bins[i] = 0.f;
        if (t < 256) slab[t] = lab[b*NP + rg*256 + t];
        if (t >= 256 && t < 256+64) scnt[t-256] = 0;
        __syncthreads();

        if (t < 256) {
            int d = chunk*256 + t;
            const float* fb = feat + ((size_t)(b*NP + rg*256))*ND + d;
            #pragma unroll 1
            for (int pp = 0; pp < 256; pp += 4) {
                int l0 = slab[pp+0], l1 = slab[pp+1], l2 = slab[pp+2], l3 = slab[pp+3];
                float v0 = fb[(size_t)(pp+0)*ND];
                float v1 = fb[(size_t)(pp+1)*ND];
                float v2 = fb[(size_t)(pp+2)*ND];
                float v3 = fb[(size_t)(pp+3)*ND];
                bins[l0*256 + t] += v0;
                bins[l1*256 + t] += v1;
                bins[l2*256 + t] += v2;
                bins[l3*256 + t] += v3;
            }
        } else if (chunk == 0) {
            // threads 256..511 count labels (shared atomics)
            atomicAdd(&scnt[slab[t-256]], 1);
        }
        __syncthreads();

        if (t < 256) {
            int d = chunk*256 + t;
            #pragma unroll 1
            for (int l = 0; l < NS; l++)
                g_sums16[(((size_t)rg*NB + b)*NS + l)*ND + d] = bins[l*256 + t];
        }
        if (chunk == 0 && t < NS)
            g_cnt16[(rg*NB + b)*NS + t] = (float)scnt[t];

    } else if (bx < 256) {
        // ============== PREP role: Gram row i ==============================
        float* red = (float*)sm_raw;           // 512
        int i  = bx - 192;
        int j  = t & 63;
        int s8 = t >> 6;                       // 0..7, 96 elems each
        const float4* wi4 = (const float4*)(W2 + (size_t)i*ND + s8*96);
        const float4* wj4 = (const float4*)(W2 + (size_t)j*ND + s8*96);
        float a0 = 0.f, a1 = 0.f;
        #pragma unroll
        for (int q = 0; q < 24; q += 2) {
            float4 x0 = wi4[q],   y0 = wj4[q];
            float4 x1 = wi4[q+1], y1 = wj4[q+1];
            a0 = fmaf(x0.x,y0.x, fmaf(x0.y,y0.y, fmaf(x0.z,y0.z, fmaf(x0.w,y0.w, a0))));
            a1 = fmaf(x1.x,y1.x, fmaf(x1.y,y1.y, fmaf(x1.z,y1.z, fmaf(x1.w,y1.w, a1))));
        }
        red[t] = a0 + a1; __syncthreads();
        if (t < 256) red[t] += red[t+256]; __syncthreads();
        if (t < 128) red[t] += red[t+128]; __syncthreads();
        if (t <  64) g_G[i*NHG + t] = red[t] + red[t+64];
        __syncthreads();

        // u_i, c_i over full row i
        const float* wi = W2 + (size_t)i*ND;
        float su = 0.f, sc = 0.f;
        for (int d = t; d < ND; d += 512) { float w = wi[d]; su += w; sc = fmaf(w, b2[d], sc); }
        float tu = red512(su, red, t);
        float tc = red512(sc, red, t);
        if (t == 0) { g_u[i] = tu * (1.f/ND); g_c[i] = tc; }

        if (i == 0) {
            float s2 = 0.f, sb = 0.f;
            for (int d = t; d < ND; d += 512) { float bv = b2[d]; s2 = fmaf(bv,bv,s2); sb += bv; }
            float t2 = red512(s2, red, t);
            float tb = red512(sb, red, t);
            if (t == 0) { g_sb2 = t2; g_bm = tb * (1.f/ND); }
        }

    } else {
        // ============== KNN role: warp per query ==========================
        float4* sh = (float4*)sm_raw;          // 1024 float4 = 16KB
        int qb = bx - 256;
        int b  = qb >> 8;
        int w  = t >> 5, lane = t & 31;
        int q  = (qb & 255)*16 + w;
        const float* cb = coords + (size_t)b*NP*3;
        float qx = cb[q*3+0], qy = cb[q*3+1], qz = cb[q*3+2];

        u64 arr[9];
        #pragma unroll
        for (int i = 0; i < 9; i++) arr[i] = ~0ull;

        for (int tile = 0; tile < 4; tile++) {
            __syncthreads();
            for (int i = t; i < 1024; i += 512) {
                int jj = tile*1024 + i;
                sh[i] = make_float4(cb[jj*3+0], cb[jj*3+1], cb[jj*3+2], 0.f);
            }
            __syncthreads();
            #pragma unroll 4
            for (int j = lane; j < 1024; j += 32) {
                float4 c = sh[j];
                float dx = qx - c.x, dy = qy - c.y, dz = qz - c.z;
                float d2 = fmaf(dx,dx, fmaf(dy,dy, dz*dz));
                int jj = tile*1024 + j;
                u64 u = ((u64)__float_as_uint(d2) << 32) | (unsigned)jj;
                if (u < arr[8]) {
                    arr[8] = u;
                    #pragma unroll
                    for (int p = 8; p > 0; p--) {
                        u64 a = arr[p-1], bb = arr[p];
                        if (bb < a) { arr[p] = a; arr[p-1] = bb; }
                    }
                }
            }
        }

        int* dst = g_knn + ((size_t)(b*NP + q))*NK;
        #pragma unroll
        for (int r = 0; r < 9; r++) {
            u64 m = arr[0];
            #pragma unroll
            for (int o = 16; o; o >>= 1) {
                u64 ot = __shfl_xor_sync(0xffffffffu, m, o);
                m = (ot < m) ? ot : m;
            }
            bool win = (arr[0] == m);
            if (win) {
                #pragma unroll
                for (int p = 0; p < 8; p++) arr[p] = arr[p+1];
                arr[8] = ~0ull;
            }
            if (lane == 0 && r > 0) dst[r-1] = (int)(m & 0xffffffffull);
        }
    }
}

// ---------------------------------------------------------------------------
// superpoint MLP: reduce slices -> means -> relu(ln(.@A1)) -> ln(.@A2) -> g_agg
// ---------------------------------------------------------------------------
__global__ __launch_bounds__(256) void k_agg(
    const float* __restrict__ A1, const float* __restrict__ ab1,
    const float* __restrict__ ag1, const float* __restrict__ abt1,
    const float* __restrict__ A2, const float* __restrict__ ab2,
    const float* __restrict__ ag2, const float* __restrict__ abt2)
{
    __shared__ float mrow[ND];
    __shared__ float ah[NH];
    __shared__ float y2[ND];
    __shared__ float red_m, red_i, s_cnt;
    int row = blockIdx.x;          // b*S + l
    int b = row >> 6, l = row & 63;
    int t = threadIdx.x;

    if (t == 0) {
        float c = 0.f;
        #pragma unroll
        for (int r = 0; r < NRG; r++) c += g_cnt16[(r*NB + b)*NS + l];
        g_cnt[row] = c;
        s_cnt = c;
    }
    __syncthreads();
    float inv_den = 1.f / fmaxf(s_cnt, 1.f);
    for (int d = t; d < ND; d += 256) {
        float s = 0.f;
        #pragma unroll
        for (int r = 0; r < NRG; r++)
            s += g_sums16[(((size_t)r*NB + b)*NS + l)*ND + d];
        mrow[d] = s * inv_den;
    }
    __syncthreads();

    // layer 1 split-k: pair of threads per output
    {
        int o = t >> 1, half = t & 1;
        float a0=0.f,a1=0.f,a2=0.f,a3=0.f;
        int d0 = half*384;
        #pragma unroll 4
        for (int d = d0; d < d0+384; d += 4) {
            a0 = fmaf(mrow[d+0], A1[(d+0)*NH + o], a0);
            a1 = fmaf(mrow[d+1], A1[(d+1)*NH + o], a1);
            a2 = fmaf(mrow[d+2], A1[(d+2)*NH + o], a2);
            a3 = fmaf(mrow[d+3], A1[(d+3)*NH + o], a3);
        }
        float acc = (a0+a1) + (a2+a3);
        acc += __shfl_xor_sync(0xffffffffu, acc, 1);
        if (!half) ah[o] = acc + ab1[o];
    }
    __syncthreads();
    if (t < 32) {
        float s = 0.f, ss = 0.f;
        #pragma unroll
        for (int q = 0; q < 4; q++) { float v = ah[t + 32*q]; s += v; ss = fmaf(v, v, ss); }
        #pragma unroll
        for (int o = 16; o; o >>= 1) { s += __shfl_xor_sync(0xffffffffu, s, o); ss += __shfl_xor_sync(0xffffffffu, ss, o); }
        if (t == 0) { float m = s*(1.f/NH); red_m = m; red_i = rsqrtf(ss*(1.f/NH) - m*m + LNEPS); }
    }
    __syncthreads();
    if (t < NH) {
        float v = fmaf((ah[t]-red_m)*red_i, ag1[t], abt1[t]);
        ah[t] = fmaxf(v, 0.f);
    }
    __syncthreads();

    // layer 2
    for (int d = t; d < ND; d += 256) {
        float a0 = ab2[d], a1 = 0.f;
        #pragma unroll 4
        for (int j = 0; j < NH; j += 2) {
            a0 = fmaf(ah[j],   A2[j*ND + d],     a0);
            a1 = fmaf(ah[j+1], A2[(j+1)*ND + d], a1);
        }
        y2[d] = a0 + a1;
    }
    __syncthreads();
    if (t < 32) {
        float s = 0.f, ss = 0.f;
        #pragma unroll
        for (int q = 0; q < 24; q++) { float v = y2[t + 32*q]; s += v; ss = fmaf(v, v, ss); }
        #pragma unroll
        for (int o = 16; o; o >>= 1) { s += __shfl_xor_sync(0xffffffffu, s, o); ss += __shfl_xor_sync(0xffffffffu, ss, o); }
        if (t == 0) { float m = s*(1.f/ND); red_m = m; red_i = rsqrtf(ss*(1.f/ND) - m*m + LNEPS); }
    }
    __syncthreads();
    for (int d = t; d < ND; d += 256)
        g_agg[(size_t)row*ND + d] = fmaf((y2[d]-red_m)*red_i, ag2[d], abt2[d]);
}

// ---------------------------------------------------------------------------
// fused main kernel (Gram trick): 16 points / block, 256 threads
// ---------------------------------------------------------------------------
__global__ __launch_bounds__(256, 2) void k_main(
    const float* __restrict__ coords, const float* __restrict__ feat,
    const int* __restrict__ lab,
    const float* __restrict__ W1, const float* __restrict__ b1,
    const float* __restrict__ g1, const float* __restrict__ bt1,
    const float* __restrict__ W2, const float* __restrict__ b2,
    const float* __restrict__ g2, const float* __restrict__ bt2,
    float* __restrict__ out)
{
    extern __shared__ float sm[];
    float* sG   = sm;               // 4096
    float* hbar = sG + 4096;        // 1024  (16 x 64)
    float* hT   = hbar + 1024;      // 8320  (64 x 130, [j][pk])
    float* sinv = hT + 8320;        // 128
    float* smn  = sinv + 128;       // 128
    float* sS1  = smn + 128;        // 16
    float* sS2  = sS1 + 16;         // 16
    float* sCnt = sS2 + 16;         // 16
    int*   sLab = (int*)(sCnt + 16);// 16
    float* sW1  = (float*)(sLab + 16); // 256
    float* sb1  = sW1 + 256;        // 64
    float* sg1  = sb1 + 64;         // 64
    float* sbt1 = sg1 + 64;         // 64
    float* su   = sbt1 + 64;        // 64
    float* sc   = su + 64;          // 64

    const int t = threadIdx.x;
    const int p0 = blockIdx.x * 16;
    const int b  = blockIdx.x >> 8;          // 256 blocks per batch

    // ---- phase 0: stage params ----
    #pragma unroll
    for (int i = 0; i < 16; i++) sG[t + 256*i] = g_G[t + 256*i];
    sW1[t] = W1[t];
    if (t < 64) { sb1[t] = b1[t]; sg1[t] = g1[t]; sbt1[t] = bt1[t]; su[t] = g_u[t]; sc[t] = g_c[t]; }
    if (t < 16) {
        int l = lab[p0 + t];
        sLab[t] = l;
        sCnt[t] = g_cnt[b*NS + l];
    }
    __syncthreads();

    // ---- phase 1: geometry -> h (LN+relu), 2 threads per (p,k) row ----
    {
        int pk = t >> 1, jb = (t & 1) * 32;
        int p = pk >> 3, kk = pk & 7;
        int gp = p0 + p;
        int ni = g_knn[gp*NK + kk];
        const float* cq = coords + (size_t)gp*3;
        const float* cn = coords + ((size_t)b*NP + ni)*3;
        float dx = cn[0]-cq[0], dy = cn[1]-cq[1], dz = cn[2]-cq[2];
        float rd = sqrtf(fmaf(dx,dx, fmaf(dy,dy, dz*dz)));
        float gm0 = rd, gm1 = dx, gm2 = dy, gm3 = fminf(rd, 1.f);

        float hv[32];
        float s = 0.f, ss = 0.f;
        #pragma unroll
        for (int jo = 0; jo < 32; jo++) {
            int j = jb + jo;
            float v = sb1[j];
            v = fmaf(gm0, sW1[j],       v);
            v = fmaf(gm1, sW1[64 + j],  v);
            v = fmaf(gm2, sW1[128 + j], v);
            v = fmaf(gm3, sW1[192 + j], v);
            hv[jo] = v;
            s += v; ss = fmaf(v, v, ss);
        }
        s  += __shfl_xor_sync(0xffffffffu, s, 1);
        ss += __shfl_xor_sync(0xffffffffu, ss, 1);
        float m = s * (1.f/NHG);
        float iv = rsqrtf(ss*(1.f/NHG) - m*m + LNEPS);
        #pragma unroll
        for (int jo = 0; jo < 32; jo++) {
            int j = jb + jo;
            float h = fmaxf(fmaf((hv[jo]-m)*iv, sg1[j], sbt1[j]), 0.f);
            hT[j*130 + pk] = h;
        }
    }
    __syncthreads();

    // ---- phase 2: LN stats from Gram (4 threads per row, 2 row-halves) ----
    {
        int q4i = t & 3, rowi = t >> 2;      // rowi 0..63
        int jb = q4i * 16;
        #pragma unroll 1
        for (int rh = 0; rh < 2; rh++) {
            int pk = rh*64 + rowi;
            float acc[16];
            #pragma unroll
            for (int jo = 0; jo < 16; jo++) acc[jo] = 0.f;
            #pragma unroll 4
            for (int i = 0; i < 64; i++) {
                float hv = hT[i*130 + pk];
                const float4* gr = reinterpret_cast<const float4*>(sG + i*64 + jb);
                float4 g0 = gr[0], g1v = gr[1], g2v = gr[2], g3 = gr[3];
                acc[ 0] = fmaf(hv, g0.x,  acc[ 0]);
                acc[ 1] = fmaf(hv, g0.y,  acc[ 1]);
                acc[ 2] = fmaf(hv, g0.z,  acc[ 2]);
                acc[ 3] = fmaf(hv, g0.w,  acc[ 3]);
                acc[ 4] = fmaf(hv, g1v.x, acc[ 4]);
                acc[ 5] = fmaf(hv, g1v.y, acc[ 5]);
                acc[ 6] = fmaf(hv, g1v.z, acc[ 6]);
                acc[ 7] = fmaf(hv, g1v.w, acc[ 7]);
                acc[ 8] = fmaf(hv, g2v.x, acc[ 8]);
                acc[ 9] = fmaf(hv, g2v.y, acc[ 9]);
                acc[10] = fmaf(hv, g2v.z, acc[10]);
                acc[11] = fmaf(hv, g2v.w, acc[11]);
                acc[12] = fmaf(hv, g3.x,  acc[12]);
                acc[13] = fmaf(hv, g3.y,  acc[13]);
                acc[14] = fmaf(hv, g3.z,  acc[14]);
                acc[15] = fmaf(hv, g3.w,  acc[15]);
            }
            float qh = 0.f, mh = 0.f, ch = 0.f;
            #pragma unroll
            for (int jo = 0; jo < 16; jo++) {
                int j = jb + jo;
                float hj = hT[j*130 + pk];
                qh = fmaf(acc[jo], hj, qh);
                mh = fmaf(hj, su[j], mh);
                ch = fmaf(hj, sc[j], ch);
            }
            #pragma unroll
            for (int o = 1; o < 4; o <<= 1) {
                qh += __shfl_xor_sync(0xffffffffu, qh, o);
                mh += __shfl_xor_sync(0xffffffffu, mh, o);
                ch += __shfl_xor_sync(0xffffffffu, ch, o);
            }
            if (q4i == 0) {
                float m  = mh + g_bm;
                float e2 = (qh + 2.f*ch + g_sb2) * (1.f/ND);
                sinv[pk] = rsqrtf(e2 - m*m + LNEPS);
                smn[pk]  = m;
            }
        }
    }
    __syncthreads();

    // ---- phase 3: hbar = sum_k inv_k h_k ; S1, S2 ----
    {
        #pragma unroll
        for (int qq = 0; qq < 4; qq++) {
            int o = t*4 + qq;
            int p = o >> 6, j = o & 63;
            float a = 0.f;
            #pragma unroll
            for (int k = 0; k < NK; k++)
                a = fmaf(sinv[p*NK + k], hT[j*130 + p*NK + k], a);
            hbar[p*64 + j] = a;
        }
        if (t < 16) {
            float s1 = 0.f, s2 = 0.f;
            #pragma unroll
            for (int k = 0; k < NK; k++) {
                float iv = sinv[t*NK + k];
                s1 += iv;
                s2 = fmaf(iv, smn[t*NK + k], s2);
            }
            sS1[t] = s1; sS2[t] = s2;
        }
    }
    __syncthreads();

    // ---- phase 4: gctx GEMM (hbar @ W2, chunked W2) + epilogue ----
    #pragma unroll 1
    for (int pass = 0; pass < 3; pass++) {
        int d = pass*256 + t;
        float pdot[16];
        #pragma unroll
        for (int p = 0; p < 16; p++) pdot[p] = 0.f;

        #pragma unroll 1
        for (int half = 0; half < 2; half++) {
            float w[32];
            #pragma unroll
            for (int j = 0; j < 32; j++) w[j] = W2[(half*32 + j)*ND + d];
            #pragma unroll 2
            for (int p = 0; p < 16; p++) {
                const float4* hb = reinterpret_cast<const float4*>(hbar + (p << 6) + half*32);
                float a0 = 0.f, a1 = 0.f, a2 = 0.f, a3 = 0.f;
                #pragma unroll
                for (int q4 = 0; q4 < 8; q4 += 4) {
                    float4 u0 = hb[q4], u1 = hb[q4+1], u2 = hb[q4+2], u3 = hb[q4+3];
                    a0 = fmaf(u0.x, w[4*q4+ 0], fmaf(u0.y, w[4*q4+ 1], fmaf(u0.z, w[4*q4+ 2], fmaf(u0.w, w[4*q4+ 3], a0))));
                    a1 = fmaf(u1.x, w[4*q4+ 4], fmaf(u1.y, w[4*q4+ 5], fmaf(u1.z, w[4*q4+ 6], fmaf(u1.w, w[4*q4+ 7], a1))));
                    a2 = fmaf(u2.x, w[4*q4+ 8], fmaf(u2.y, w[4*q4+ 9], fmaf(u2.z, w[4*q4+10], fmaf(u2.w, w[4*q4+11], a2))));
                    a3 = fmaf(u3.x, w[4*q4+12], fmaf(u3.y, w[4*q4+13], fmaf(u3.z, w[4*q4+14], fmaf(u3.w, w[4*q4+15], a3))));
                }
                pdot[p] += (a0 + a1) + (a2 + a3);
            }
        }

        float bb = b2[d], gg = g2[d], bt = bt2[d];
        #pragma unroll
        for (int p = 0; p < 16; p++) {
            float f  = feat[(size_t)(p0+p)*ND + d];
            float gc = (pdot[p] + fmaf(bb, sS1[p], -sS2[p])) * 0.125f;
            float enc = fmaf(gc, gg, bt);
            int   l   = sLab[p];
            float a   = g_agg[((size_t)(b*NS + l))*ND + d];
            float e   = (sCnt[p] >= 2.f) ? fmaf(0.1f, a, 0.9f*f) : f;
            out[(size_t)(p0+p)*ND + d] = fmaf(0.1f, enc, e);
        }
    }
}

// ---------------------------------------------------------------------------
extern "C" void kernel_launch(void* const* d_in, const int* in_sizes, int n_in,
                              void* d_out, int out_size) {
    const float* coords = (const float*)d_in[0];
    const float* feat   = (const float*)d_in[1];
    const int*   lab    = (const int*)  d_in[2];
    const float* W1     = (const float*)d_in[3];
    const float* b1     = (const float*)d_in[4];
    const float* g1     = (const float*)d_in[5];
    const float* bt1    = (const float*)d_in[6];
    const float* W2     = (const float*)d_in[7];
    const float* b2     = (const float*)d_in[8];
    const float* g2     = (const float*)d_in[9];
    const float* bt2    = (const float*)d_in[10];
    const float* A1     = (const float*)d_in[11];
    const float* ab1    = (const float*)d_in[12];
    const float* ag1    = (const float*)d_in[13];
    const float* abt1   = (const float*)d_in[14];
    const float* A2     = (const float*)d_in[15];
    const float* ab2    = (const float*)d_in[16];
    const float* ag2    = (const float*)d_in[17];
    const float* abt2   = (const float*)d_in[18];
    float* out = (float*)d_out;

    const int SMEM_PRE  = NS*256*4 + 256*4 + 64*4;   // 66816 B
    const int SMEM_MAIN = 14336 * 4;                 // 57344 B
    static int smem_set = 0;
    if (!smem_set) {
        cudaFuncSetAttribute(k_pre,  cudaFuncAttributeMaxDynamicSharedMemorySize, SMEM_PRE);
        cudaFuncSetAttribute(k_main, cudaFuncAttributeMaxDynamicSharedMemorySize, SMEM_MAIN);
        smem_set = 1;
    }

    k_pre <<<1280, 512, SMEM_PRE>>>(coords, feat, lab, W2, b2);
    k_agg <<<NB*NS, 256>>>(A1, ab1, ag1, abt1, A2, ab2, ag2, abt2);
    k_main<<<(NB*NP)/16, 256, SMEM_MAIN>>>(coords, feat, lab,
                                           W1, b1, g1, bt1, W2, b2, g2, bt2, out);
}

// round 4
// speedup vs baseline: 3.2073x; 1.4277x over previous
#include <cuda_runtime.h>
#include <math.h>
#include <float.h>

#define NB 4
#define NP 4096
#define ND 768
#define NK 8
#define NH 128
#define NS 64
#define NHG 64
#define NRG 16
#define LNEPS 1e-5f

typedef unsigned long long u64;

// ---- scratch (no allocations allowed) ----
__device__ float g_sums16[NRG*NB*NS*ND];   // per-range segment sums (written fully)
__device__ float g_cnt16 [NRG*NB*NS];
__device__ float g_cnt   [NB*NS];          // totals (written by k_agg)
__device__ float g_agg   [NB*NS*ND];
__device__ int   g_knn   [NB*NP*NK];
__device__ float g_G     [NHG*NHG];        // W2 @ W2^T
__device__ float g_u     [NHG];            // mean_d W2[j,d]
__device__ float g_c     [NHG];            // sum_d W2[j,d]*b2[d]
__device__ float g_sb2;                    // sum_d b2[d]^2
__device__ float g_bm;                     // mean(b2)

// ---------------------------------------------------------------------------
__device__ __forceinline__ float red512(float v, float* red, int t) {
    red[t] = v; __syncthreads();
    if (t < 256) red[t] += red[t+256]; __syncthreads();
    if (t < 128) red[t] += red[t+128]; __syncthreads();
    if (t <  64) red[t] += red[t+ 64]; __syncthreads();
    if (t <  32) {
        float s = red[t] + red[t+32];
        #pragma unroll
        for (int o = 16; o; o >>= 1) s += __shfl_xor_sync(0xffffffffu, s, o);
        if (t == 0) red[0] = s;
    }
    __syncthreads();
    float r = red[0];
    __syncthreads();
    return r;
}

// ---------------------------------------------------------------------------
// FUSED front-end kernel: blocks [0,192) seg, [192,256) prep, [256,1280) knn
// ---------------------------------------------------------------------------
__global__ __launch_bounds__(512) void k_pre(
    const float* __restrict__ coords, const float* __restrict__ feat,
    const int* __restrict__ lab,
    const float* __restrict__ W2, const float* __restrict__ b2)
{
    extern __shared__ char sm_raw[];
    const int bx = blockIdx.x;
    const int t  = threadIdx.x;

    if (bx < 192) {
        // ============== SEG role ==========================================
        float* bins = (float*)sm_raw;          // 64*256
        int*   slab = (int*)(bins + NS*256);   // 256
        int*   scnt = slab + 256;              // 64
        int chunk = bx >> 6;
        int rem   = bx & 63;
        int rg    = rem >> 2;
        int b     = rem & 3;

        for (int i = t; i < NS*256; i += 512) bins[i] = 0.f;
        if (t < 256) slab[t] = lab[b*NP + rg*256 + t];
        if (t >= 256 && t < 256+64) scnt[t-256] = 0;
        __syncthreads();

        if (t < 256) {
            int d = chunk*256 + t;
            const float* fb = feat + ((size_t)(b*NP + rg*256))*ND + d;
            #pragma unroll 1
            for (int pp = 0; pp < 256; pp += 4) {
                int l0 = slab[pp+0], l1 = slab[pp+1], l2 = slab[pp+2], l3 = slab[pp+3];
                float v0 = fb[(size_t)(pp+0)*ND];
                float v1 = fb[(size_t)(pp+1)*ND];
                float v2 = fb[(size_t)(pp+2)*ND];
                float v3 = fb[(size_t)(pp+3)*ND];
                bins[l0*256 + t] += v0;
                bins[l1*256 + t] += v1;
                bins[l2*256 + t] += v2;
                bins[l3*256 + t] += v3;
            }
        } else if (chunk == 0) {
            atomicAdd(&scnt[slab[t-256]], 1);
        }
        __syncthreads();

        if (t < 256) {
            int d = chunk*256 + t;
            #pragma unroll 1
            for (int l = 0; l < NS; l++)
                g_sums16[(((size_t)rg*NB + b)*NS + l)*ND + d] = bins[l*256 + t];
        }
        if (chunk == 0 && t < NS)
            g_cnt16[(rg*NB + b)*NS + t] = (float)scnt[t];

    } else if (bx < 256) {
        // ============== PREP role: Gram row i =============================
        float* red = (float*)sm_raw;
        int i  = bx - 192;
        int j  = t & 63;
        int s8 = t >> 6;
        const float4* wi4 = (const float4*)(W2 + (size_t)i*ND + s8*96);
        const float4* wj4 = (const float4*)(W2 + (size_t)j*ND + s8*96);
        float a0 = 0.f, a1 = 0.f;
        #pragma unroll
        for (int q = 0; q < 24; q += 2) {
            float4 x0 = wi4[q],   y0 = wj4[q];
            float4 x1 = wi4[q+1], y1 = wj4[q+1];
            a0 = fmaf(x0.x,y0.x, fmaf(x0.y,y0.y, fmaf(x0.z,y0.z, fmaf(x0.w,y0.w, a0))));
            a1 = fmaf(x1.x,y1.x, fmaf(x1.y,y1.y, fmaf(x1.z,y1.z, fmaf(x1.w,y1.w, a1))));
        }
        red[t] = a0 + a1; __syncthreads();
        if (t < 256) red[t] += red[t+256]; __syncthreads();
        if (t < 128) red[t] += red[t+128]; __syncthreads();
        if (t <  64) g_G[i*NHG + t] = red[t] + red[t+64];
        __syncthreads();

        const float* wi = W2 + (size_t)i*ND;
        float su = 0.f, sc = 0.f;
        for (int d = t; d < ND; d += 512) { float w = wi[d]; su += w; sc = fmaf(w, b2[d], sc); }
        float tu = red512(su, red, t);
        float tc = red512(sc, red, t);
        if (t == 0) { g_u[i] = tu * (1.f/ND); g_c[i] = tc; }

        if (i == 0) {
            float s2 = 0.f, sb = 0.f;
            for (int d = t; d < ND; d += 512) { float bv = b2[d]; s2 = fmaf(bv,bv,s2); sb += bv; }
            float t2 = red512(s2, red, t);
            float tb = red512(sb, red, t);
            if (t == 0) { g_sb2 = t2; g_bm = tb * (1.f/ND); }
        }

    } else {
        // ============== KNN role: warp per query, 2-pass threshold ========
        float4* sh  = (float4*)sm_raw;                       // 16384 B
        u64*    buf = (u64*)(sm_raw + 16384);                // 16*32*8 = 4096 B
        int*    bcnt= (int*)(sm_raw + 16384 + 4096);         // 16 ints
        int qb = bx - 256;
        int b  = qb >> 8;
        int w  = t >> 5, lane = t & 31;
        int q  = (qb & 255)*16 + w;
        const float* cb = coords + (size_t)b*NP*3;
        float qx = cb[q*3+0], qy = cb[q*3+1], qz = cb[q*3+2];

        // ---- pass 1: branchless per-lane top-3 of d2 (keys only) ----
        float a0 = FLT_MAX, a1 = FLT_MAX, a2 = FLT_MAX;
        for (int tile = 0; tile < 4; tile++) {
            __syncthreads();
            for (int i = t; i < 1024; i += 512) {
                int jj = tile*1024 + i;
                sh[i] = make_float4(cb[jj*3+0], cb[jj*3+1], cb[jj*3+2], 0.f);
            }
            __syncthreads();
            #pragma unroll 4
            for (int j = lane; j < 1024; j += 32) {
                float4 c = sh[j];
                float dx = qx - c.x, dy = qy - c.y, dz = qz - c.z;
                float d2 = fmaf(dx,dx, fmaf(dy,dy, dz*dz));
                float lo = fminf(a0, d2); d2 = fmaxf(a0, d2); a0 = lo;
                lo = fminf(a1, d2); d2 = fmaxf(a1, d2); a1 = lo;
                a2 = fminf(a2, d2);
            }
        }

        // ---- merge: T = 9th smallest of the 96-value union (>= true 9th) ----
        float T = 0.f;
        {
            float h0 = a0, h1 = a1, h2 = a2;
            #pragma unroll
            for (int r = 0; r < 9; r++) {
                float m = h0;
                #pragma unroll
                for (int o = 16; o; o >>= 1)
                    m = fminf(m, __shfl_xor_sync(0xffffffffu, m, o));
                if (h0 == m) { h0 = h1; h1 = h2; h2 = FLT_MAX; }
                T = m;
            }
        }

        if (lane == 0) bcnt[w] = 0;
        __syncwarp();

        // ---- pass 2: collect all candidates with d2 <= T ----
        for (int tile = 0; tile < 4; tile++) {
            __syncthreads();
            for (int i = t; i < 1024; i += 512) {
                int jj = tile*1024 + i;
                sh[i] = make_float4(cb[jj*3+0], cb[jj*3+1], cb[jj*3+2], 0.f);
            }
            __syncthreads();
            #pragma unroll 4
            for (int j = lane; j < 1024; j += 32) {
                float4 c = sh[j];
                float dx = qx - c.x, dy = qy - c.y, dz = qz - c.z;
                float d2 = fmaf(dx,dx, fmaf(dy,dy, dz*dz));
                if (d2 <= T) {
                    int pos = atomicAdd(&bcnt[w], 1);
                    if (pos < 32)
                        buf[w*32 + pos] = ((u64)__float_as_uint(d2) << 32)
                                        | (unsigned)(tile*1024 + j);
                }
            }
        }
        __syncwarp();

        // ---- exact rank select on (d2,idx) keys; emit ranks 1..8 ----
        int cnt = min(bcnt[w], 32);
        u64 mine = (lane < cnt) ? buf[w*32 + lane] : ~0ull;
        int rank = 0;
        for (int i = 0; i < cnt; i++)
            rank += (buf[w*32 + i] < mine) ? 1 : 0;
        int* dst = g_knn + ((size_t)(b*NP + q))*NK;
        if (lane < cnt && rank >= 1 && rank <= 8)
            dst[rank-1] = (int)(mine & 0xffffffffull);
    }
}

// ---------------------------------------------------------------------------
// superpoint MLP
// ---------------------------------------------------------------------------
__global__ __launch_bounds__(256) void k_agg(
    const float* __restrict__ A1, const float* __restrict__ ab1,
    const float* __restrict__ ag1, const float* __restrict__ abt1,
    const float* __restrict__ A2, const float* __restrict__ ab2,
    const float* __restrict__ ag2, const float* __restrict__ abt2)
{
    __shared__ float mrow[ND];
    __shared__ float ah[NH];
    __shared__ float y2[ND];
    __shared__ float red_m, red_i, s_cnt;
    int row = blockIdx.x;
    int b = row >> 6, l = row & 63;
    int t = threadIdx.x;

    if (t == 0) {
        float c = 0.f;
        #pragma unroll
        for (int r = 0; r < NRG; r++) c += g_cnt16[(r*NB + b)*NS + l];
        g_cnt[row] = c;
        s_cnt = c;
    }
    __syncthreads();
    float inv_den = 1.f / fmaxf(s_cnt, 1.f);
    for (int d = t; d < ND; d += 256) {
        float s = 0.f;
        #pragma unroll
        for (int r = 0; r < NRG; r++)
            s += g_sums16[(((size_t)r*NB + b)*NS + l)*ND + d];
        mrow[d] = s * inv_den;
    }
    __syncthreads();

    {
        int o = t >> 1, half = t & 1;
        float a0=0.f,a1=0.f,a2=0.f,a3=0.f;
        int d0 = half*384;
        #pragma unroll 4
        for (int d = d0; d < d0+384; d += 4) {
            a0 = fmaf(mrow[d+0], A1[(d+0)*NH + o], a0);
            a1 = fmaf(mrow[d+1], A1[(d+1)*NH + o], a1);
            a2 = fmaf(mrow[d+2], A1[(d+2)*NH + o], a2);
            a3 = fmaf(mrow[d+3], A1[(d+3)*NH + o], a3);
        }
        float acc = (a0+a1) + (a2+a3);
        acc += __shfl_xor_sync(0xffffffffu, acc, 1);
        if (!half) ah[o] = acc + ab1[o];
    }
    __syncthreads();
    if (t < 32) {
        float s = 0.f, ss = 0.f;
        #pragma unroll
        for (int q = 0; q < 4; q++) { float v = ah[t + 32*q]; s += v; ss = fmaf(v, v, ss); }
        #pragma unroll
        for (int o = 16; o; o >>= 1) { s += __shfl_xor_sync(0xffffffffu, s, o); ss += __shfl_xor_sync(0xffffffffu, ss, o); }
        if (t == 0) { float m = s*(1.f/NH); red_m = m; red_i = rsqrtf(ss*(1.f/NH) - m*m + LNEPS); }
    }
    __syncthreads();
    if (t < NH) {
        float v = fmaf((ah[t]-red_m)*red_i, ag1[t], abt1[t]);
        ah[t] = fmaxf(v, 0.f);
    }
    __syncthreads();

    for (int d = t; d < ND; d += 256) {
        float a0 = ab2[d], a1 = 0.f;
        #pragma unroll 4
        for (int j = 0; j < NH; j += 2) {
            a0 = fmaf(ah[j],   A2[j*ND + d],     a0);
            a1 = fmaf(ah[j+1], A2[(j+1)*ND + d], a1);
        }
        y2[d] = a0 + a1;
    }
    __syncthreads();
    if (t < 32) {
        float s = 0.f, ss = 0.f;
        #pragma unroll
        for (int q = 0; q < 24; q++) { float v = y2[t + 32*q]; s += v; ss = fmaf(v, v, ss); }
        #pragma unroll
        for (int o = 16; o; o >>= 1) { s += __shfl_xor_sync(0xffffffffu, s, o); ss += __shfl_xor_sync(0xffffffffu, ss, o); }
        if (t == 0) { float m = s*(1.f/ND); red_m = m; red_i = rsqrtf(ss*(1.f/ND) - m*m + LNEPS); }
    }
    __syncthreads();
    for (int d = t; d < ND; d += 256)
        g_agg[(size_t)row*ND + d] = fmaf((y2[d]-red_m)*red_i, ag2[d], abt2[d]);
}

// ---------------------------------------------------------------------------
// fused main kernel (Gram trick): 16 points / block, 256 threads
// ---------------------------------------------------------------------------
__global__ __launch_bounds__(256, 2) void k_main(
    const float* __restrict__ coords, const float* __restrict__ feat,
    const int* __restrict__ lab,
    const float* __restrict__ W1, const float* __restrict__ b1,
    const float* __restrict__ g1, const float* __restrict__ bt1,
    const float* __restrict__ W2, const float* __restrict__ b2,
    const float* __restrict__ g2, const float* __restrict__ bt2,
    float* __restrict__ out)
{
    extern __shared__ float sm[];
    float* sG   = sm;               // 4096
    float* hbar = sG + 4096;        // 1024
    float* hT   = hbar + 1024;      // 8320
    float* sinv = hT + 8320;        // 128
    float* smn  = sinv + 128;       // 128
    float* sS1  = smn + 128;        // 16
    float* sS2  = sS1 + 16;         // 16
    float* sCnt = sS2 + 16;         // 16
    int*   sLab = (int*)(sCnt + 16);// 16
    float* sW1  = (float*)(sLab + 16); // 256
    float* sb1  = sW1 + 256;        // 64
    float* sg1  = sb1 + 64;         // 64
    float* sbt1 = sg1 + 64;         // 64
    float* su   = sbt1 + 64;        // 64
    float* sc   = su + 64;          // 64

    const int t = threadIdx.x;
    const int p0 = blockIdx.x * 16;
    const int b  = blockIdx.x >> 8;

    #pragma unroll
    for (int i = 0; i < 16; i++) sG[t + 256*i] = g_G[t + 256*i];
    sW1[t] = W1[t];
    if (t < 64) { sb1[t] = b1[t]; sg1[t] = g1[t]; sbt1[t] = bt1[t]; su[t] = g_u[t]; sc[t] = g_c[t]; }
    if (t < 16) {
        int l = lab[p0 + t];
        sLab[t] = l;
        sCnt[t] = g_cnt[b*NS + l];
    }
    __syncthreads();

    {
        int pk = t >> 1, jb = (t & 1) * 32;
        int p = pk >> 3, kk = pk & 7;
        int gp = p0 + p;
        int ni = g_knn[gp*NK + kk];
        const float* cq = coords + (size_t)gp*3;
        const float* cn = coords + ((size_t)b*NP + ni)*3;
        float dx = cn[0]-cq[0], dy = cn[1]-cq[1], dz = cn[2]-cq[2];
        float rd = sqrtf(fmaf(dx,dx, fmaf(dy,dy, dz*dz)));
        float gm0 = rd, gm1 = dx, gm2 = dy, gm3 = fminf(rd, 1.f);

        float hv[32];
        float s = 0.f, ss = 0.f;
        #pragma unroll
        for (int jo = 0; jo < 32; jo++) {
            int j = jb + jo;
            float v = sb1[j];
            v = fmaf(gm0, sW1[j],       v);
            v = fmaf(gm1, sW1[64 + j],  v);
            v = fmaf(gm2, sW1[128 + j], v);
            v = fmaf(gm3, sW1[192 + j], v);
            hv[jo] = v;
            s += v; ss = fmaf(v, v, ss);
        }
        s  += __shfl_xor_sync(0xffffffffu, s, 1);
        ss += __shfl_xor_sync(0xffffffffu, ss, 1);
        float m = s * (1.f/NHG);
        float iv = rsqrtf(ss*(1.f/NHG) - m*m + LNEPS);
        #pragma unroll
        for (int jo = 0; jo < 32; jo++) {
            int j = jb + jo;
            float h = fmaxf(fmaf((hv[jo]-m)*iv, sg1[j], sbt1[j]), 0.f);
            hT[j*130 + pk] = h;
        }
    }
    __syncthreads();

    {
        int q4i = t & 3, rowi = t >> 2;
        int jb = q4i * 16;
        #pragma unroll 1
        for (int rh = 0; rh < 2; rh++) {
            int pk = rh*64 + rowi;
            float acc[16];
            #pragma unroll
            for (int jo = 0; jo < 16; jo++) acc[jo] = 0.f;
            #pragma unroll 4
            for (int i = 0; i < 64; i++) {
                float hv = hT[i*130 + pk];
                const float4* gr = reinterpret_cast<const float4*>(sG + i*64 + jb);
                float4 g0 = gr[0], g1v = gr[1], g2v = gr[2], g3 = gr[3];
                acc[ 0] = fmaf(hv, g0.x,  acc[ 0]);
                acc[ 1] = fmaf(hv, g0.y,  acc[ 1]);
                acc[ 2] = fmaf(hv, g0.z,  acc[ 2]);
                acc[ 3] = fmaf(hv, g0.w,  acc[ 3]);
                acc[ 4] = fmaf(hv, g1v.x, acc[ 4]);
                acc[ 5] = fmaf(hv, g1v.y, acc[ 5]);
                acc[ 6] = fmaf(hv, g1v.z, acc[ 6]);
                acc[ 7] = fmaf(hv, g1v.w, acc[ 7]);
                acc[ 8] = fmaf(hv, g2v.x, acc[ 8]);
                acc[ 9] = fmaf(hv, g2v.y, acc[ 9]);
                acc[10] = fmaf(hv, g2v.z, acc[10]);
                acc[11] = fmaf(hv, g2v.w, acc[11]);
                acc[12] = fmaf(hv, g3.x,  acc[12]);
                acc[13] = fmaf(hv, g3.y,  acc[13]);
                acc[14] = fmaf(hv, g3.z,  acc[14]);
                acc[15] = fmaf(hv, g3.w,  acc[15]);
            }
            float qh = 0.f, mh = 0.f, ch = 0.f;
            #pragma unroll
            for (int jo = 0; jo < 16; jo++) {
                int j = jb + jo;
                float hj = hT[j*130 + pk];
                qh = fmaf(acc[jo], hj, qh);
                mh = fmaf(hj, su[j], mh);
                ch = fmaf(hj, sc[j], ch);
            }
            #pragma unroll
            for (int o = 1; o < 4; o <<= 1) {
                qh += __shfl_xor_sync(0xffffffffu, qh, o);
                mh += __shfl_xor_sync(0xffffffffu, mh, o);
                ch += __shfl_xor_sync(0xffffffffu, ch, o);
            }
            if (q4i == 0) {
                float m  = mh + g_bm;
                float e2 = (qh + 2.f*ch + g_sb2) * (1.f/ND);
                sinv[pk] = rsqrtf(e2 - m*m + LNEPS);
                smn[pk]  = m;
            }
        }
    }
    __syncthreads();

    {
        #pragma unroll
        for (int qq = 0; qq < 4; qq++) {
            int o = t*4 + qq;
            int p = o >> 6, j = o & 63;
            float a = 0.f;
            #pragma unroll
            for (int k = 0; k < NK; k++)
                a = fmaf(sinv[p*NK + k], hT[j*130 + p*NK + k], a);
            hbar[p*64 + j] = a;
        }
        if (t < 16) {
            float s1 = 0.f, s2 = 0.f;
            #pragma unroll
            for (int k = 0; k < NK; k++) {
                float iv = sinv[t*NK + k];
                s1 += iv;
                s2 = fmaf(iv, smn[t*NK + k], s2);
            }
            sS1[t] = s1; sS2[t] = s2;
        }
    }
    __syncthreads();

    #pragma unroll 1
    for (int pass = 0; pass < 3; pass++) {
        int d = pass*256 + t;
        float pdot[16];
        #pragma unroll
        for (int p = 0; p < 16; p++) pdot[p] = 0.f;

        #pragma unroll 1
        for (int half = 0; half < 2; half++) {
            float w[32];
            #pragma unroll
            for (int j = 0; j < 32; j++) w[j] = W2[(half*32 + j)*ND + d];
            #pragma unroll 2
            for (int p = 0; p < 16; p++) {
                const float4* hb = reinterpret_cast<const float4*>(hbar + (p << 6) + half*32);
                float a0 = 0.f, a1 = 0.f, a2 = 0.f, a3 = 0.f;
                #pragma unroll
                for (int q4 = 0; q4 < 8; q4 += 4) {
                    float4 u0 = hb[q4], u1 = hb[q4+1], u2 = hb[q4+2], u3 = hb[q4+3];
                    a0 = fmaf(u0.x, w[4*q4+ 0], fmaf(u0.y, w[4*q4+ 1], fmaf(u0.z, w[4*q4+ 2], fmaf(u0.w, w[4*q4+ 3], a0))));
                    a1 = fmaf(u1.x, w[4*q4+ 4], fmaf(u1.y, w[4*q4+ 5], fmaf(u1.z, w[4*q4+ 6], fmaf(u1.w, w[4*q4+ 7], a1))));
                    a2 = fmaf(u2.x, w[4*q4+ 8], fmaf(u2.y, w[4*q4+ 9], fmaf(u2.z, w[4*q4+10], fmaf(u2.w, w[4*q4+11], a2))));
                    a3 = fmaf(u3.x, w[4*q4+12], fmaf(u3.y, w[4*q4+13], fmaf(u3.z, w[4*q4+14], fmaf(u3.w, w[4*q4+15], a3))));
                }
                pdot[p] += (a0 + a1) + (a2 + a3);
            }
        }

        float bb = b2[d], gg = g2[d], bt = bt2[d];
        #pragma unroll
        for (int p = 0; p < 16; p++) {
            float f  = feat[(size_t)(p0+p)*ND + d];
            float gc = (pdot[p] + fmaf(bb, sS1[p], -sS2[p])) * 0.125f;
            float enc = fmaf(gc, gg, bt);
            int   l   = sLab[p];
            float a   = g_agg[((size_t)(b*NS + l))*ND + d];
            float e   = (sCnt[p] >= 2.f) ? fmaf(0.1f, a, 0.9f*f) : f;
            out[(size_t)(p0+p)*ND + d] = fmaf(0.1f, enc, e);
        }
    }
}

// ---------------------------------------------------------------------------
extern "C" void kernel_launch(void* const* d_in, const int* in_sizes, int n_in,
                              void* d_out, int out_size) {
    const float* coords = (const float*)d_in[0];
    const float* feat   = (const float*)d_in[1];
    const int*   lab    = (const int*)  d_in[2];
    const float* W1     = (const float*)d_in[3];
    const float* b1     = (const float*)d_in[4];
    const float* g1     = (const float*)d_in[5];
    const float* bt1    = (const float*)d_in[6];
    const float* W2     = (const float*)d_in[7];
    const float* b2     = (const float*)d_in[8];
    const float* g2     = (const float*)d_in[9];
    const float* bt2    = (const float*)d_in[10];
    const float* A1     = (const float*)d_in[11];
    const float* ab1    = (const float*)d_in[12];
    const float* ag1    = (const float*)d_in[13];
    const float* abt1   = (const float*)d_in[14];
    const float* A2     = (const float*)d_in[15];
    const float* ab2    = (const float*)d_in[16];
    const float* ag2    = (const float*)d_in[17];
    const float* abt2   = (const float*)d_in[18];
    float* out = (float*)d_out;

    const int SMEM_PRE  = NS*256*4 + 256*4 + 64*4;   // 66816 B
    const int SMEM_MAIN = 14336 * 4;                 // 57344 B
    static int smem_set = 0;
    if (!smem_set) {
        cudaFuncSetAttribute(k_pre,  cudaFuncAttributeMaxDynamicSharedMemorySize, SMEM_PRE);
        cudaFuncSetAttribute(k_main, cudaFuncAttributeMaxDynamicSharedMemorySize, SMEM_MAIN);
        smem_set = 1;
    }

    k_pre <<<1280, 512, SMEM_PRE>>>(coords, feat, lab, W2, b2);
    k_agg <<<NB*NS, 256>>>(A1, ab1, ag1, abt1, A2, ab2, ag2, abt2);
    k_main<<<(NB*NP)/16, 256, SMEM_MAIN>>>(coords, feat, lab,
                                           W1, b1, g1, bt1, W2, b2, g2, bt2, out);
}

// round 5
// speedup vs baseline: 3.3463x; 1.0433x over previous
#include <cuda_runtime.h>
#include <math.h>
#include <float.h>

#define NB 4
#define NP 4096
#define ND 768
#define NK 8
#define NH 128
#define NS 64
#define NHG 64
#define NRG 16
#define LNEPS 1e-5f

typedef unsigned long long u64;

// ---- scratch (no allocations allowed) ----
__device__ float g_sums16[NRG*NB*NS*ND];
__device__ float g_cnt16 [NRG*NB*NS];
__device__ float g_cnt   [NB*NS];
__device__ float g_agg   [NB*NS*ND];
__device__ int   g_knn   [NB*NP*NK];
__device__ float g_G     [NHG*NHG];
__device__ float g_u     [NHG];
__device__ float g_c     [NHG];
__device__ float g_sb2;
__device__ float g_bm;
__device__ float g_hbar  [NB*NP*NHG];      // 4 MB
__device__ float g_S1    [NB*NP];
__device__ float g_S2    [NB*NP];

// ---------------------------------------------------------------------------
__device__ __forceinline__ float red512(float v, float* red, int t) {
    red[t] = v; __syncthreads();
    if (t < 256) red[t] += red[t+256]; __syncthreads();
    if (t < 128) red[t] += red[t+128]; __syncthreads();
    if (t <  64) red[t] += red[t+ 64]; __syncthreads();
    if (t <  32) {
        float s = red[t] + red[t+32];
        #pragma unroll
        for (int o = 16; o; o >>= 1) s += __shfl_xor_sync(0xffffffffu, s, o);
        if (t == 0) red[0] = s;
    }
    __syncthreads();
    float r = red[0];
    __syncthreads();
    return r;
}

// ---------------------------------------------------------------------------
// FUSED front-end kernel: blocks [0,192) seg, [192,256) prep, [256,1280) knn
// ---------------------------------------------------------------------------
__global__ __launch_bounds__(512) void k_pre(
    const float* __restrict__ coords, const float* __restrict__ feat,
    const int* __restrict__ lab,
    const float* __restrict__ W2, const float* __restrict__ b2)
{
    extern __shared__ char sm_raw[];
    const int bx = blockIdx.x;
    const int t  = threadIdx.x;

    if (bx < 192) {
        // ============== SEG role ==========================================
        float* bins = (float*)sm_raw;
        int*   slab = (int*)(bins + NS*256);
        int*   scnt = slab + 256;
        int chunk = bx >> 6;
        int rem   = bx & 63;
        int rg    = rem >> 2;
        int b     = rem & 3;

        for (int i = t; i < NS*256; i += 512) bins[i] = 0.f;
        if (t < 256) slab[t] = lab[b*NP + rg*256 + t];
        if (t >= 256 && t < 256+64) scnt[t-256] = 0;
        __syncthreads();

        if (t < 256) {
            int d = chunk*256 + t;
            const float* fb = feat + ((size_t)(b*NP + rg*256))*ND + d;
            #pragma unroll 1
            for (int pp = 0; pp < 256; pp += 4) {
                int l0 = slab[pp+0], l1 = slab[pp+1], l2 = slab[pp+2], l3 = slab[pp+3];
                float v0 = fb[(size_t)(pp+0)*ND];
                float v1 = fb[(size_t)(pp+1)*ND];
                float v2 = fb[(size_t)(pp+2)*ND];
                float v3 = fb[(size_t)(pp+3)*ND];
                bins[l0*256 + t] += v0;
                bins[l1*256 + t] += v1;
                bins[l2*256 + t] += v2;
                bins[l3*256 + t] += v3;
            }
        } else if (chunk == 0) {
            atomicAdd(&scnt[slab[t-256]], 1);
        }
        __syncthreads();

        if (t < 256) {
            int d = chunk*256 + t;
            #pragma unroll 1
            for (int l = 0; l < NS; l++)
                g_sums16[(((size_t)rg*NB + b)*NS + l)*ND + d] = bins[l*256 + t];
        }
        if (chunk == 0 && t < NS)
            g_cnt16[(rg*NB + b)*NS + t] = (float)scnt[t];

    } else if (bx < 256) {
        // ============== PREP role: Gram row i =============================
        float* red = (float*)sm_raw;
        int i  = bx - 192;
        int j  = t & 63;
        int s8 = t >> 6;
        const float4* wi4 = (const float4*)(W2 + (size_t)i*ND + s8*96);
        const float4* wj4 = (const float4*)(W2 + (size_t)j*ND + s8*96);
        float a0 = 0.f, a1 = 0.f;
        #pragma unroll
        for (int q = 0; q < 24; q += 2) {
            float4 x0 = wi4[q],   y0 = wj4[q];
            float4 x1 = wi4[q+1], y1 = wj4[q+1];
            a0 = fmaf(x0.x,y0.x, fmaf(x0.y,y0.y, fmaf(x0.z,y0.z, fmaf(x0.w,y0.w, a0))));
            a1 = fmaf(x1.x,y1.x, fmaf(x1.y,y1.y, fmaf(x1.z,y1.z, fmaf(x1.w,y1.w, a1))));
        }
        red[t] = a0 + a1; __syncthreads();
        if (t < 256) red[t] += red[t+256]; __syncthreads();
        if (t < 128) red[t] += red[t+128]; __syncthreads();
        if (t <  64) g_G[i*NHG + t] = red[t] + red[t+64];
        __syncthreads();

        const float* wi = W2 + (size_t)i*ND;
        float su = 0.f, sc = 0.f;
        for (int d = t; d < ND; d += 512) { float w = wi[d]; su += w; sc = fmaf(w, b2[d], sc); }
        float tu = red512(su, red, t);
        float tc = red512(sc, red, t);
        if (t == 0) { g_u[i] = tu * (1.f/ND); g_c[i] = tc; }

        if (i == 0) {
            float s2 = 0.f, sb = 0.f;
            for (int d = t; d < ND; d += 512) { float bv = b2[d]; s2 = fmaf(bv,bv,s2); sb += bv; }
            float t2 = red512(s2, red, t);
            float tb = red512(sb, red, t);
            if (t == 0) { g_sb2 = t2; g_bm = tb * (1.f/ND); }
        }

    } else {
        // ============== KNN role: warp per query, 2-pass threshold ========
        float4* sh  = (float4*)sm_raw;
        u64*    buf = (u64*)(sm_raw + 16384);
        int*    bcnt= (int*)(sm_raw + 16384 + 4096);
        int qb = bx - 256;
        int b  = qb >> 8;
        int w  = t >> 5, lane = t & 31;
        int q  = (qb & 255)*16 + w;
        const float* cb = coords + (size_t)b*NP*3;
        float qx = cb[q*3+0], qy = cb[q*3+1], qz = cb[q*3+2];

        float a0 = FLT_MAX, a1 = FLT_MAX, a2 = FLT_MAX;
        for (int tile = 0; tile < 4; tile++) {
            __syncthreads();
            for (int i = t; i < 1024; i += 512) {
                int jj = tile*1024 + i;
                sh[i] = make_float4(cb[jj*3+0], cb[jj*3+1], cb[jj*3+2], 0.f);
            }
            __syncthreads();
            #pragma unroll 4
            for (int j = lane; j < 1024; j += 32) {
                float4 c = sh[j];
                float dx = qx - c.x, dy = qy - c.y, dz = qz - c.z;
                float d2 = fmaf(dx,dx, fmaf(dy,dy, dz*dz));
                float lo = fminf(a0, d2); d2 = fmaxf(a0, d2); a0 = lo;
                lo = fminf(a1, d2); d2 = fmaxf(a1, d2); a1 = lo;
                a2 = fminf(a2, d2);
            }
        }

        float T = 0.f;
        {
            float h0 = a0, h1 = a1, h2 = a2;
            #pragma unroll
            for (int r = 0; r < 9; r++) {
                float m = h0;
                #pragma unroll
                for (int o = 16; o; o >>= 1)
                    m = fminf(m, __shfl_xor_sync(0xffffffffu, m, o));
                if (h0 == m) { h0 = h1; h1 = h2; h2 = FLT_MAX; }
                T = m;
            }
        }

        if (lane == 0) bcnt[w] = 0;
        __syncwarp();

        for (int tile = 0; tile < 4; tile++) {
            __syncthreads();
            for (int i = t; i < 1024; i += 512) {
                int jj = tile*1024 + i;
                sh[i] = make_float4(cb[jj*3+0], cb[jj*3+1], cb[jj*3+2], 0.f);
            }
            __syncthreads();
            #pragma unroll 4
            for (int j = lane; j < 1024; j += 32) {
                float4 c = sh[j];
                float dx = qx - c.x, dy = qy - c.y, dz = qz - c.z;
                float d2 = fmaf(dx,dx, fmaf(dy,dy, dz*dz));
                if (d2 <= T) {
                    int pos = atomicAdd(&bcnt[w], 1);
                    if (pos < 32)
                        buf[w*32 + pos] = ((u64)__float_as_uint(d2) << 32)
                                        | (unsigned)(tile*1024 + j);
                }
            }
        }
        __syncwarp();

        int cnt = min(bcnt[w], 32);
        u64 mine = (lane < cnt) ? buf[w*32 + lane] : ~0ull;
        int rank = 0;
        for (int i = 0; i < cnt; i++)
            rank += (buf[w*32 + i] < mine) ? 1 : 0;
        int* dst = g_knn + ((size_t)(b*NP + q))*NK;
        if (lane < cnt && rank >= 1 && rank <= 8)
            dst[rank-1] = (int)(mine & 0xffffffffull);
    }
}

// ---------------------------------------------------------------------------
// superpoint MLP
// ---------------------------------------------------------------------------
__global__ __launch_bounds__(256) void k_agg(
    const float* __restrict__ A1, const float* __restrict__ ab1,
    const float* __restrict__ ag1, const float* __restrict__ abt1,
    const float* __restrict__ A2, const float* __restrict__ ab2,
    const float* __restrict__ ag2, const float* __restrict__ abt2)
{
    __shared__ float mrow[ND];
    __shared__ float ah[NH];
    __shared__ float y2[ND];
    __shared__ float red_m, red_i, s_cnt;
    int row = blockIdx.x;
    int b = row >> 6, l = row & 63;
    int t = threadIdx.x;

    if (t == 0) {
        float c = 0.f;
        #pragma unroll
        for (int r = 0; r < NRG; r++) c += g_cnt16[(r*NB + b)*NS + l];
        g_cnt[row] = c;
        s_cnt = c;
    }
    __syncthreads();
    float inv_den = 1.f / fmaxf(s_cnt, 1.f);
    for (int d = t; d < ND; d += 256) {
        float s = 0.f;
        #pragma unroll
        for (int r = 0; r < NRG; r++)
            s += g_sums16[(((size_t)r*NB + b)*NS + l)*ND + d];
        mrow[d] = s * inv_den;
    }
    __syncthreads();

    {
        int o = t >> 1, half = t & 1;
        float a0=0.f,a1=0.f,a2=0.f,a3=0.f;
        int d0 = half*384;
        #pragma unroll 4
        for (int d = d0; d < d0+384; d += 4) {
            a0 = fmaf(mrow[d+0], A1[(d+0)*NH + o], a0);
            a1 = fmaf(mrow[d+1], A1[(d+1)*NH + o], a1);
            a2 = fmaf(mrow[d+2], A1[(d+2)*NH + o], a2);
            a3 = fmaf(mrow[d+3], A1[(d+3)*NH + o], a3);
        }
        float acc = (a0+a1) + (a2+a3);
        acc += __shfl_xor_sync(0xffffffffu, acc, 1);
        if (!half) ah[o] = acc + ab1[o];
    }
    __syncthreads();
    if (t < 32) {
        float s = 0.f, ss = 0.f;
        #pragma unroll
        for (int q = 0; q < 4; q++) { float v = ah[t + 32*q]; s += v; ss = fmaf(v, v, ss); }
        #pragma unroll
        for (int o = 16; o; o >>= 1) { s += __shfl_xor_sync(0xffffffffu, s, o); ss += __shfl_xor_sync(0xffffffffu, ss, o); }
        if (t == 0) { float m = s*(1.f/NH); red_m = m; red_i = rsqrtf(ss*(1.f/NH) - m*m + LNEPS); }
    }
    __syncthreads();
    if (t < NH) {
        float v = fmaf((ah[t]-red_m)*red_i, ag1[t], abt1[t]);
        ah[t] = fmaxf(v, 0.f);
    }
    __syncthreads();

    for (int d = t; d < ND; d += 256) {
        float a0 = ab2[d], a1 = 0.f;
        #pragma unroll 4
        for (int j = 0; j < NH; j += 2) {
            a0 = fmaf(ah[j],   A2[j*ND + d],     a0);
            a1 = fmaf(ah[j+1], A2[(j+1)*ND + d], a1);
        }
        y2[d] = a0 + a1;
    }
    __syncthreads();
    if (t < 32) {
        float s = 0.f, ss = 0.f;
        #pragma unroll
        for (int q = 0; q < 24; q++) { float v = y2[t + 32*q]; s += v; ss = fmaf(v, v, ss); }
        #pragma unroll
        for (int o = 16; o; o >>= 1) { s += __shfl_xor_sync(0xffffffffu, s, o); ss += __shfl_xor_sync(0xffffffffu, ss, o); }
        if (t == 0) { float m = s*(1.f/ND); red_m = m; red_i = rsqrtf(ss*(1.f/ND) - m*m + LNEPS); }
    }
    __syncthreads();
    for (int d = t; d < ND; d += 256)
        g_agg[(size_t)row*ND + d] = fmaf((y2[d]-red_m)*red_i, ag2[d], abt2[d]);
}

// ---------------------------------------------------------------------------
// k_stats: geometry -> h -> Gram LN stats -> hbar/S1/S2 (phases 0-3)
// 16 points / block, 256 threads
// ---------------------------------------------------------------------------
__global__ __launch_bounds__(256, 2) void k_stats(
    const float* __restrict__ coords,
    const float* __restrict__ W1, const float* __restrict__ b1,
    const float* __restrict__ g1, const float* __restrict__ bt1)
{
    extern __shared__ float sm[];
    float* sG   = sm;               // 4096
    float* hT   = sG + 4096;        // 8320
    float* sinv = hT + 8320;        // 128
    float* smn  = sinv + 128;       // 128
    float* sW1  = smn + 128;        // 256
    float* sb1  = sW1 + 256;        // 64
    float* sg1  = sb1 + 64;         // 64
    float* sbt1 = sg1 + 64;         // 64
    float* su   = sbt1 + 64;        // 64
    float* sc   = su + 64;          // 64

    const int t = threadIdx.x;
    const int p0 = blockIdx.x * 16;
    const int b  = blockIdx.x >> 8;

    #pragma unroll
    for (int i = 0; i < 16; i++) sG[t + 256*i] = g_G[t + 256*i];
    sW1[t] = W1[t];
    if (t < 64) { sb1[t] = b1[t]; sg1[t] = g1[t]; sbt1[t] = bt1[t]; su[t] = g_u[t]; sc[t] = g_c[t]; }
    __syncthreads();

    // phase 1: geometry -> h (LN+relu), 2 threads per (p,k) row
    {
        int pk = t >> 1, jb = (t & 1) * 32;
        int p = pk >> 3, kk = pk & 7;
        int gp = p0 + p;
        int ni = g_knn[gp*NK + kk];
        const float* cq = coords + (size_t)gp*3;
        const float* cn = coords + ((size_t)b*NP + ni)*3;
        float dx = cn[0]-cq[0], dy = cn[1]-cq[1], dz = cn[2]-cq[2];
        float rd = sqrtf(fmaf(dx,dx, fmaf(dy,dy, dz*dz)));
        float gm0 = rd, gm1 = dx, gm2 = dy, gm3 = fminf(rd, 1.f);

        float hv[32];
        float s = 0.f, ss = 0.f;
        #pragma unroll
        for (int jo = 0; jo < 32; jo++) {
            int j = jb + jo;
            float v = sb1[j];
            v = fmaf(gm0, sW1[j],       v);
            v = fmaf(gm1, sW1[64 + j],  v);
            v = fmaf(gm2, sW1[128 + j], v);
            v = fmaf(gm3, sW1[192 + j], v);
            hv[jo] = v;
            s += v; ss = fmaf(v, v, ss);
        }
        s  += __shfl_xor_sync(0xffffffffu, s, 1);
        ss += __shfl_xor_sync(0xffffffffu, ss, 1);
        float m = s * (1.f/NHG);
        float iv = rsqrtf(ss*(1.f/NHG) - m*m + LNEPS);
        #pragma unroll
        for (int jo = 0; jo < 32; jo++) {
            int j = jb + jo;
            float h = fmaxf(fmaf((hv[jo]-m)*iv, sg1[j], sbt1[j]), 0.f);
            hT[j*130 + pk] = h;
        }
    }
    __syncthreads();

    // phase 2: LN stats from Gram (4 threads per row, 2 row-halves)
    {
        int q4i = t & 3, rowi = t >> 2;
        int jb = q4i * 16;
        #pragma unroll 1
        for (int rh = 0; rh < 2; rh++) {
            int pk = rh*64 + rowi;
            float acc[16];
            #pragma unroll
            for (int jo = 0; jo < 16; jo++) acc[jo] = 0.f;
            #pragma unroll 4
            for (int i = 0; i < 64; i++) {
                float hv = hT[i*130 + pk];
                const float4* gr = reinterpret_cast<const float4*>(sG + i*64 + jb);
                float4 g0 = gr[0], g1v = gr[1], g2v = gr[2], g3 = gr[3];
                acc[ 0] = fmaf(hv, g0.x,  acc[ 0]);
                acc[ 1] = fmaf(hv, g0.y,  acc[ 1]);
                acc[ 2] = fmaf(hv, g0.z,  acc[ 2]);
                acc[ 3] = fmaf(hv, g0.w,  acc[ 3]);
                acc[ 4] = fmaf(hv, g1v.x, acc[ 4]);
                acc[ 5] = fmaf(hv, g1v.y, acc[ 5]);
                acc[ 6] = fmaf(hv, g1v.z, acc[ 6]);
                acc[ 7] = fmaf(hv, g1v.w, acc[ 7]);
                acc[ 8] = fmaf(hv, g2v.x, acc[ 8]);
                acc[ 9] = fmaf(hv, g2v.y, acc[ 9]);
                acc[10] = fmaf(hv, g2v.z, acc[10]);
                acc[11] = fmaf(hv, g2v.w, acc[11]);
                acc[12] = fmaf(hv, g3.x,  acc[12]);
                acc[13] = fmaf(hv, g3.y,  acc[13]);
                acc[14] = fmaf(hv, g3.z,  acc[14]);
                acc[15] = fmaf(hv, g3.w,  acc[15]);
            }
            float qh = 0.f, mh = 0.f, ch = 0.f;
            #pragma unroll
            for (int jo = 0; jo < 16; jo++) {
                int j = jb + jo;
                float hj = hT[j*130 + pk];
                qh = fmaf(acc[jo], hj, qh);
                mh = fmaf(hj, su[j], mh);
                ch = fmaf(hj, sc[j], ch);
            }
            #pragma unroll
            for (int o = 1; o < 4; o <<= 1) {
                qh += __shfl_xor_sync(0xffffffffu, qh, o);
                mh += __shfl_xor_sync(0xffffffffu, mh, o);
                ch += __shfl_xor_sync(0xffffffffu, ch, o);
            }
            if (q4i == 0) {
                float m  = mh + g_bm;
                float e2 = (qh + 2.f*ch + g_sb2) * (1.f/ND);
                sinv[pk] = rsqrtf(e2 - m*m + LNEPS);
                smn[pk]  = m;
            }
        }
    }
    __syncthreads();

    // phase 3: hbar -> global; S1/S2 -> global
    {
        #pragma unroll
        for (int qq = 0; qq < 4; qq++) {
            int o = t*4 + qq;
            int p = o >> 6;
            int j = o & 63;
            float a = 0.f;
            #pragma unroll
            for (int k = 0; k < NK; k++)
                a = fmaf(sinv[p*NK + k], hT[j*130 + p*NK + k], a);
            g_hbar[(size_t)p0*NHG + o] = a;
        }
        if (t < 16) {
            float s1 = 0.f, s2 = 0.f;
            #pragma unroll
            for (int k = 0; k < NK; k++) {
                float iv = sinv[t*NK + k];
                s1 += iv;
                s2 = fmaf(iv, smn[t*NK + k], s2);
            }
            g_S1[p0 + t] = s1;
            g_S2[p0 + t] = s2;
        }
    }
}

// ---------------------------------------------------------------------------
// k_gemm: gctx = (hbar @ W2 + b*S1 - S2)/8 -> LN affine -> blend -> out
// 16 points / block, 384 threads (each owns d and d+384)
// ---------------------------------------------------------------------------
__global__ __launch_bounds__(384, 2) void k_gemm(
    const float* __restrict__ feat, const int* __restrict__ lab,
    const float* __restrict__ W2, const float* __restrict__ b2,
    const float* __restrict__ g2, const float* __restrict__ bt2,
    float* __restrict__ out)
{
    __shared__ float sh[16*NHG];
    __shared__ float sS1[16], sS2[16], sCnt[16];
    __shared__ int   sLab[16];
    const int t  = threadIdx.x;
    const int p0 = blockIdx.x * 16;
    const int b  = blockIdx.x >> 8;

    for (int i = t; i < 16*NHG; i += 384) sh[i] = g_hbar[(size_t)p0*NHG + i];
    if (t < 16) {
        int l = lab[p0 + t];
        sLab[t] = l;
        sCnt[t] = g_cnt[b*NS + l];
        sS1[t]  = g_S1[p0 + t];
        sS2[t]  = g_S2[p0 + t];
    }
    __syncthreads();

    const int d0 = t, d1 = t + 384;
    float pd0[16], pd1[16];
    #pragma unroll
    for (int p = 0; p < 16; p++) { pd0[p] = 0.f; pd1[p] = 0.f; }

    #pragma unroll 1
    for (int c = 0; c < 8; c++) {
        float w0[8], w1[8];
        #pragma unroll
        for (int j8 = 0; j8 < 8; j8++) {
            int j = c*8 + j8;
            w0[j8] = W2[j*ND + d0];
            w1[j8] = W2[j*ND + d1];
        }
        #pragma unroll
        for (int p = 0; p < 16; p++) {
            const float4* h4 = reinterpret_cast<const float4*>(sh + p*NHG + c*8);
            float4 ha = h4[0], hb = h4[1];
            float a0, a1;
            a0 = fmaf(ha.x, w0[0], fmaf(ha.y, w0[1], fmaf(ha.z, w0[2], fmaf(ha.w, w0[3], pd0[p]))));
            pd0[p] = fmaf(hb.x, w0[4], fmaf(hb.y, w0[5], fmaf(hb.z, w0[6], fmaf(hb.w, w0[7], a0))));
            a1 = fmaf(ha.x, w1[0], fmaf(ha.y, w1[1], fmaf(ha.z, w1[2], fmaf(ha.w, w1[3], pd1[p]))));
            pd1[p] = fmaf(hb.x, w1[4], fmaf(hb.y, w1[5], fmaf(hb.z, w1[6], fmaf(hb.w, w1[7], a1))));
        }
    }

    float bb0 = b2[d0], gg0 = g2[d0], bt0 = bt2[d0];
    float bb1 = b2[d1], gg1 = g2[d1], bt1v = bt2[d1];
    #pragma unroll 2
    for (int p = 0; p < 16; p++) {
        int gp = p0 + p;
        int l  = sLab[p];
        bool agg_on = (sCnt[p] >= 2.f);
        const float* ar = g_agg + ((size_t)(b*NS + l))*ND;
        const float* fr = feat + (size_t)gp*ND;
        float*       orow = out + (size_t)gp*ND;

        float f0 = fr[d0];
        float gc0 = (pd0[p] + fmaf(bb0, sS1[p], -sS2[p])) * 0.125f;
        float enc0 = fmaf(gc0, gg0, bt0);
        float e0 = agg_on ? fmaf(0.1f, ar[d0], 0.9f*f0) : f0;
        orow[d0] = fmaf(0.1f, enc0, e0);

        float f1 = fr[d1];
        float gc1 = (pd1[p] + fmaf(bb1, sS1[p], -sS2[p])) * 0.125f;
        float enc1 = fmaf(gc1, gg1, bt1v);
        float e1 = agg_on ? fmaf(0.1f, ar[d1], 0.9f*f1) : f1;
        orow[d1] = fmaf(0.1f, enc1, e1);
    }
}

// ---------------------------------------------------------------------------
extern "C" void kernel_launch(void* const* d_in, const int* in_sizes, int n_in,
                              void* d_out, int out_size) {
    const float* coords = (const float*)d_in[0];
    const float* feat   = (const float*)d_in[1];
    const int*   lab    = (const int*)  d_in[2];
    const float* W1     = (const float*)d_in[3];
    const float* b1     = (const float*)d_in[4];
    const float* g1     = (const float*)d_in[5];
    const float* bt1    = (const float*)d_in[6];
    const float* W2     = (const float*)d_in[7];
    const float* b2     = (const float*)d_in[8];
    const float* g2     = (const float*)d_in[9];
    const float* bt2    = (const float*)d_in[10];
    const float* A1     = (const float*)d_in[11];
    const float* ab1    = (const float*)d_in[12];
    const float* ag1    = (const float*)d_in[13];
    const float* abt1   = (const float*)d_in[14];
    const float* A2     = (const float*)d_in[15];
    const float* ab2    = (const float*)d_in[16];
    const float* ag2    = (const float*)d_in[17];
    const float* abt2   = (const float*)d_in[18];
    float* out = (float*)d_out;

    const int SMEM_PRE   = NS*256*4 + 256*4 + 64*4;   // 66816 B
    const int SMEM_STATS = (4096 + 8320 + 128 + 128 + 256 + 64*5) * 4;  // 53056 B
    static int smem_set = 0;
    if (!smem_set) {
        cudaFuncSetAttribute(k_pre,   cudaFuncAttributeMaxDynamicSharedMemorySize, SMEM_PRE);
        cudaFuncSetAttribute(k_stats, cudaFuncAttributeMaxDynamicSharedMemorySize, SMEM_STATS);
        smem_set = 1;
    }

    k_pre  <<<1280, 512, SMEM_PRE>>>(coords, feat, lab, W2, b2);
    k_agg  <<<NB*NS, 256>>>(A1, ab1, ag1, abt1, A2, ab2, ag2, abt2);
    k_stats<<<(NB*NP)/16, 256, SMEM_STATS>>>(coords, W1, b1, g1, bt1);
    k_gemm <<<(NB*NP)/16, 384>>>(feat, lab, W2, b2, g2, bt2, out);
}